// round 10
// baseline (speedup 1.0000x reference)
#include <cuda_runtime.h>
#include <cstdint>

#define T_STEPS 128
#define B_SZ    128
#define N_RES   4096
#define IN_DIM  1024
#define MAX_DIM 4608
#define M_A     (T_STEPS * B_SZ)   // 16384 rows for phase A
#define KSPLIT  8                  // phase-B k-splits (K-chunk 512)
#define A_CHUNK_TILES 8            // phaseA m-tiles (=timesteps) per chunk
#define N_CHUNKS (T_STEPS / A_CHUNK_TILES)   // 16

// ---------------- scratch (device globals; no cudaMalloc allowed) ----------
__device__ float g_P[(size_t)M_A * N_RES];          // input_part
__device__ float g_G[(size_t)M_A * 3 * N_RES];      // gates (post-sigmoid)
__device__ float g_state[B_SZ * N_RES];             // exact recurrent state
__device__ float g_state_r[B_SZ * N_RES];           // tf32-rounded state (GEMM input)
__device__ float g_part[KSPLIT][B_SZ * N_RES];      // K-split partials

// pre-rounded (tf32-representable) operand copies
__device__ float g_x_r[(size_t)M_A * IN_DIM];
__device__ float g_Win_r[(size_t)N_RES * IN_DIM];
__device__ float g_Wgate_r[(size_t)3 * N_RES * IN_DIM];
__device__ float g_Wres_r[(size_t)N_RES * N_RES];

// ---------------- small helpers -------------------------------------------
__device__ __forceinline__ uint32_t cvt_tf32(float x) {
    uint32_t r;
    asm("cvt.rna.tf32.f32 %0, %1;" : "=r"(r) : "f"(x));
    return r;
}

__device__ __forceinline__ void mma_tf32_16x8x8(float* d, const uint32_t* a, const uint32_t* b) {
    asm volatile(
        "mma.sync.aligned.m16n8k8.row.col.f32.tf32.tf32.f32 "
        "{%0,%1,%2,%3}, {%4,%5,%6,%7}, {%8,%9}, {%0,%1,%2,%3};"
        : "+f"(d[0]), "+f"(d[1]), "+f"(d[2]), "+f"(d[3])
        : "r"(a[0]), "r"(a[1]), "r"(a[2]), "r"(a[3]), "r"(b[0]), "r"(b[1]));
}

__device__ __forceinline__ void cp16(void* sm, const void* gm) {
    uint32_t s = (uint32_t)__cvta_generic_to_shared(sm);
    asm volatile("cp.async.cg.shared.global [%0], [%1], 16;" :: "r"(s), "l"(gm));
}
#define CP_COMMIT() asm volatile("cp.async.commit_group;")
#define CP_WAIT1()  asm volatile("cp.async.wait_group 1;")

// ---------------- pre-rounding --------------------------------------------
__global__ __launch_bounds__(256) void round4_kernel(const float4* __restrict__ src,
                                                     int n4, int which) {
    float4* dst = (which == 0) ? (float4*)g_x_r
                : (which == 1) ? (float4*)g_Win_r
                : (which == 2) ? (float4*)g_Wgate_r
                               : (float4*)g_Wres_r;
    int i = blockIdx.x * 256 + threadIdx.x;
    if (i < n4) {
        float4 v = src[i];
        float4 o;
        o.x = __uint_as_float(cvt_tf32(v.x));
        o.y = __uint_as_float(cvt_tf32(v.y));
        o.z = __uint_as_float(cvt_tf32(v.z));
        o.w = __uint_as_float(cvt_tf32(v.w));
        dst[i] = o;
    }
}

// ===========================================================================
// Phase A: C[m,f] = sum_k X[m,k] * W[f,k]   (chunked over m-tiles)
// f < 4096  -> g_P (raw);  f >= 4096 -> g_G (sigmoid applied)
// 128-thread CTAs (tile 128m x 64f, 4 warps of 64x32), reg-capped to 85 so one
// phaseA CTA co-resides with two stepB CTAs (2*256*104 + 128*88 <= 64K regs).
// ===========================================================================
__global__ __launch_bounds__(128, 6) void phaseA_gemm(int tile0) {
    __shared__ uint32_t As[2][128][20];
    __shared__ uint32_t Bs[2][64][20];

    const int tid  = threadIdx.x;
    const int warp = tid >> 5, lane = tid & 31;
    const int g  = lane >> 2, tg = lane & 3;
    const int wm = warp >> 1, wn = warp & 1;            // 2 x 2 warp grid
    const int mbase = (tile0 + blockIdx.y) * 128;
    const int fblk  = blockIdx.x;                       // 0..255 (64-wide)
    const bool isP  = (fblk < 64);
    const float* W  = isP ? g_Win_r : g_Wgate_r;
    const int frow0 = isP ? fblk * 64 : (fblk - 64) * 64;

    float acc[4][4][4];
    #pragma unroll
    for (int i = 0; i < 4; i++)
        #pragma unroll
        for (int j = 0; j < 4; j++)
            #pragma unroll
            for (int c = 0; c < 4; c++) acc[i][j][c] = 0.f;

    const int NIT = IN_DIM / 16;   // 64

    auto load_stage = [&](int s, int it) {
        const int k0 = it * 16;
        #pragma unroll
        for (int r = 0; r < 4; r++) {           // A: 128 rows x 16k = 512 x 16B
            int c = tid + r * 128;
            int row = c >> 2, seg = c & 3;
            cp16(&As[s][row][seg * 4], g_x_r + (size_t)(mbase + row) * IN_DIM + k0 + seg * 4);
        }
        #pragma unroll
        for (int r = 0; r < 2; r++) {           // B: 64 rows x 16k = 256 x 16B
            int c = tid + r * 128;
            int row = c >> 2, seg = c & 3;
            cp16(&Bs[s][row][seg * 4], W + (size_t)(frow0 + row) * IN_DIM + k0 + seg * 4);
        }
    };

    load_stage(0, 0);
    CP_COMMIT();

    for (int it = 0; it < NIT; it++) {
        const int s = it & 1;
        if (it + 1 < NIT) load_stage(s ^ 1, it + 1);
        CP_COMMIT();
        CP_WAIT1();
        __syncthreads();

        #pragma unroll
        for (int kk = 0; kk < 16; kk += 8) {
            uint32_t af[4][4], bf[4][2];
            #pragma unroll
            for (int mt = 0; mt < 4; mt++) {
                const int r = wm * 64 + mt * 16 + g;
                af[mt][0] = As[s][r    ][kk + tg    ];
                af[mt][1] = As[s][r + 8][kk + tg    ];
                af[mt][2] = As[s][r    ][kk + tg + 4];
                af[mt][3] = As[s][r + 8][kk + tg + 4];
            }
            #pragma unroll
            for (int nt = 0; nt < 4; nt++) {
                const int fc = wn * 32 + nt * 8 + g;
                bf[nt][0] = Bs[s][fc][kk + tg    ];
                bf[nt][1] = Bs[s][fc][kk + tg + 4];
            }
            #pragma unroll
            for (int mt = 0; mt < 4; mt++)
                #pragma unroll
                for (int nt = 0; nt < 4; nt++)
                    mma_tf32_16x8x8(acc[mt][nt], af[mt], bf[nt]);
        }
        __syncthreads();
    }

    // epilogue
    #pragma unroll
    for (int mt = 0; mt < 4; mt++) {
        #pragma unroll
        for (int nt = 0; nt < 4; nt++) {
            const int fc = fblk * 64 + wn * 32 + nt * 8 + 2 * tg;   // global feature col
            #pragma unroll
            for (int half = 0; half < 2; half++) {
                const int m = mbase + wm * 64 + mt * 16 + g + half * 8;
                const float v0 = acc[mt][nt][half * 2 + 0];
                const float v1 = acc[mt][nt][half * 2 + 1];
                if (isP) {
                    *(float2*)&g_P[(size_t)m * N_RES + fc] = make_float2(v0, v1);
                } else {
                    float2 o = make_float2(1.f / (1.f + __expf(-v0)),
                                           1.f / (1.f + __expf(-v1)));
                    *(float2*)&g_G[(size_t)m * (3 * N_RES) + (fc - N_RES)] = o;
                }
            }
        }
    }
}

// ===========================================================================
// Phase B per-step GEMM (proven R4 kernel): R[m,n] = sum_k state_r[m,k]*W_res[k,n]
// grid = (32 n-tiles, 8 k-splits) = 256 CTAs -> 2 CTAs/SM co-resident.
// ===========================================================================
__global__ __launch_bounds__(256, 2) void stepB_gemm() {
    __shared__ uint32_t As[2][128][20];    // state rows [m][k]
    __shared__ uint32_t Bs[2][16][136];    // W_res tile [k][n]

    const int tid  = threadIdx.x;
    const int warp = tid >> 5, lane = tid & 31;
    const int g  = lane >> 2, tg = lane & 3;
    const int wm = warp >> 2, wn = warp & 3;
    const int nbase = blockIdx.x * 128;
    const int kbase = blockIdx.y * (N_RES / KSPLIT);   // 512 per split

    float acc[4][4][4];
    #pragma unroll
    for (int i = 0; i < 4; i++)
        #pragma unroll
        for (int j = 0; j < 4; j++)
            #pragma unroll
            for (int c = 0; c < 4; c++) acc[i][j][c] = 0.f;

    const int NIT = (N_RES / KSPLIT) / 16;   // 32

    auto load_stage = [&](int s, int it) {
        const int k0 = kbase + it * 16;
        #pragma unroll
        for (int r = 0; r < 2; r++) {
            int c = tid + r * 256;
            int row = c >> 2, seg = c & 3;
            cp16(&As[s][row][seg * 4], g_state_r + (size_t)row * N_RES + k0 + seg * 4);
        }
        #pragma unroll
        for (int r = 0; r < 2; r++) {
            int c = tid + r * 256;
            int kr = c >> 5, seg = c & 31;
            cp16(&Bs[s][kr][seg * 4], g_Wres_r + (size_t)(k0 + kr) * N_RES + nbase + seg * 4);
        }
    };

    load_stage(0, 0);
    CP_COMMIT();

    for (int it = 0; it < NIT; it++) {
        const int s = it & 1;
        if (it + 1 < NIT) load_stage(s ^ 1, it + 1);
        CP_COMMIT();
        CP_WAIT1();
        __syncthreads();

        #pragma unroll
        for (int kk = 0; kk < 16; kk += 8) {
            uint32_t af[4][4], bf[4][2];
            #pragma unroll
            for (int mt = 0; mt < 4; mt++) {
                const int r = wm * 64 + mt * 16 + g;
                af[mt][0] = As[s][r    ][kk + tg    ];
                af[mt][1] = As[s][r + 8][kk + tg    ];
                af[mt][2] = As[s][r    ][kk + tg + 4];
                af[mt][3] = As[s][r + 8][kk + tg + 4];
            }
            #pragma unroll
            for (int nt = 0; nt < 4; nt++) {
                const int col = wn * 32 + nt * 8 + g;
                bf[nt][0] = Bs[s][kk + tg    ][col];
                bf[nt][1] = Bs[s][kk + tg + 4][col];
            }
            #pragma unroll
            for (int mt = 0; mt < 4; mt++)
                #pragma unroll
                for (int nt = 0; nt < 4; nt++)
                    mma_tf32_16x8x8(acc[mt][nt], af[mt], bf[nt]);
        }
        __syncthreads();
    }

    float* part = g_part[blockIdx.y];
    #pragma unroll
    for (int mt = 0; mt < 4; mt++) {
        #pragma unroll
        for (int nt = 0; nt < 4; nt++) {
            const int n = nbase + wn * 32 + nt * 8 + 2 * tg;
            #pragma unroll
            for (int half = 0; half < 2; half++) {
                const int m = wm * 64 + mt * 16 + g + half * 8;
                *(float2*)&part[(size_t)m * N_RES + n] =
                    make_float2(acc[mt][nt][half * 2 + 0], acc[mt][nt][half * 2 + 1]);
            }
        }
    }
}

// ===========================================================================
// Per-step reduce + cell update + output write (deterministic, vectorized)
// ===========================================================================
__global__ __launch_bounds__(256) void update_kernel(float* __restrict__ out, int t) {
    const int n = (blockIdx.x * 256 + threadIdx.x) * 4;   // 0..4092 step 4
    const int b = blockIdx.y;
    const int idx = b * N_RES + n;

    float4 res = *(const float4*)&g_part[0][idx];
    #pragma unroll
    for (int ks = 1; ks < KSPLIT; ks++) {
        float4 p = *(const float4*)&g_part[ks][idx];
        res.x += p.x; res.y += p.y; res.z += p.z; res.w += p.w;
    }

    const float4 prev = *(const float4*)&g_state[idx];
    const size_t mrow = (size_t)t * B_SZ + b;
    const float4 pp = *(const float4*)&g_P[mrow * N_RES + n];
    const float* gr = g_G + mrow * (3 * N_RES);
    const float4 gi = *(const float4*)&gr[n];
    const float4 gf = *(const float4*)&gr[N_RES + n];
    const float4 go = *(const float4*)&gr[2 * N_RES + n];

    float4 s;
    {
        float z0 = gi.x * (pp.x + res.x), z1 = gi.y * (pp.y + res.y);
        float z2 = gi.z * (pp.z + res.z), z3 = gi.w * (pp.w + res.w);
        s.x = go.x * (0.9f * gf.x * prev.x + 0.1f * tanhf(z0));
        s.y = go.y * (0.9f * gf.y * prev.y + 0.1f * tanhf(z1));
        s.z = go.z * (0.9f * gf.z * prev.z + 0.1f * tanhf(z2));
        s.w = go.w * (0.9f * gf.w * prev.w + 0.1f * tanhf(z3));
        if (s.x > 0.5f) s.x -= 0.5f;
        if (s.y > 0.5f) s.y -= 0.5f;
        if (s.z > 0.5f) s.z -= 0.5f;
        if (s.w > 0.5f) s.w -= 0.5f;
    }

    *(float4*)&g_state[idx] = s;
    float4 sr;
    sr.x = __uint_as_float(cvt_tf32(s.x));
    sr.y = __uint_as_float(cvt_tf32(s.y));
    sr.z = __uint_as_float(cvt_tf32(s.z));
    sr.w = __uint_as_float(cvt_tf32(s.w));
    *(float4*)&g_state_r[idx] = sr;
    *(float4*)&out[mrow * MAX_DIM + n] = s;
}

// ---------------- init / padding ------------------------------------------
__global__ __launch_bounds__(256) void init_state_kernel(const float* __restrict__ state0) {
    const int n = blockIdx.x * 256 + threadIdx.x;
    const int b = blockIdx.y;
    const float v = state0[(size_t)b * MAX_DIM + n];
    g_state[b * N_RES + n]   = v;
    g_state_r[b * N_RES + n] = __uint_as_float(cvt_tf32(v));
}

__global__ __launch_bounds__(256) void pad_out_kernel(float4* __restrict__ out) {
    const int idx = blockIdx.x * 256 + threadIdx.x;   // over T*B*128 float4
    const int tb = idx >> 7;
    const int c = idx & 127;
    out[(size_t)tb * (MAX_DIM / 4) + (N_RES / 4) + c] = make_float4(0.f, 0.f, 0.f, 0.f);
}

// ===========================================================================
extern "C" void kernel_launch(void* const* d_in, const int* in_sizes, int n_in,
                              void* d_out, int out_size) {
    const float* x      = (const float*)d_in[0];   // [T,B,1024]
    const float* state0 = (const float*)d_in[1];   // [B,4608]
    const float* W_res  = (const float*)d_in[2];   // [4096,4096]
    const float* W_in   = (const float*)d_in[3];   // [4096,1024]
    const float* W_gate = (const float*)d_in[4];   // [12288,1024]
    float* out = (float*)d_out;                    // [T,B,4608]

    // ---- lazy stream/event setup (only outside capture; never device mem) --
    static cudaStream_t s2 = nullptr;
    static cudaEvent_t evFork = nullptr;
    static cudaEvent_t evChunk[N_CHUNKS];
    static bool setup_tried = false;
    static bool overlap_ok = false;
    if (!setup_tried) {
        setup_tried = true;
        cudaStreamCaptureStatus cap = cudaStreamCaptureStatusNone;
        cudaStreamIsCapturing(0, &cap);
        if (cap == cudaStreamCaptureStatusNone) {
            bool ok = (cudaStreamCreateWithFlags(&s2, cudaStreamNonBlocking) == cudaSuccess);
            ok = ok && (cudaEventCreateWithFlags(&evFork, cudaEventDisableTiming) == cudaSuccess);
            for (int c = 0; ok && c < N_CHUNKS; c++)
                ok = (cudaEventCreateWithFlags(&evChunk[c], cudaEventDisableTiming) == cudaSuccess);
            overlap_ok = ok;
        }
    }

    // ---- main stream: operand pre-rounding + state init -------------------
    round4_kernel<<<16384, 256>>>((const float4*)x,      (M_A * IN_DIM) / 4,          0);
    round4_kernel<<< 4096, 256>>>((const float4*)W_in,   (N_RES * IN_DIM) / 4,        1);
    round4_kernel<<<12288, 256>>>((const float4*)W_gate, (3 * N_RES * IN_DIM) / 4,    2);
    round4_kernel<<<16384, 256>>>((const float4*)W_res,  (N_RES * N_RES) / 4,         3);
    init_state_kernel<<<dim3(16, 128), 256>>>(state0);
    pad_out_kernel<<<8192, 256>>>((float4*)out);

    if (overlap_ok) {
        // ---- fork: phase A runs concurrently on s2, chunked by timestep ----
        cudaEventRecord(evFork, 0);
        cudaStreamWaitEvent(s2, evFork, 0);
        for (int c = 0; c < N_CHUNKS; c++) {
            phaseA_gemm<<<dim3(256, A_CHUNK_TILES), 128, 0, s2>>>(c * A_CHUNK_TILES);
            cudaEventRecord(evChunk[c], s2);
        }

        // ---- phase B on the main stream; join s2 at each chunk boundary ----
        for (int t = 0; t < T_STEPS; t++) {
            stepB_gemm<<<dim3(32, KSPLIT), 256>>>();
            if ((t % A_CHUNK_TILES) == 0)
                cudaStreamWaitEvent(0, evChunk[t / A_CHUNK_TILES], 0);
            update_kernel<<<dim3(4, 128), 256>>>(out, t);
        }
    } else {
        // ---- fallback: fully serial --------------------------------------
        for (int c = 0; c < N_CHUNKS; c++)
            phaseA_gemm<<<dim3(256, A_CHUNK_TILES), 128>>>(c * A_CHUNK_TILES);
        for (int t = 0; t < T_STEPS; t++) {
            stepB_gemm<<<dim3(32, KSPLIT), 256>>>();
            update_kernel<<<dim3(4, 128), 256>>>(out, t);
        }
    }
}

// round 12
// speedup vs baseline: 1.3048x; 1.3048x over previous
#include <cuda_runtime.h>
#include <cstdint>

#define T_STEPS 128
#define B_SZ    128
#define N_RES   4096
#define IN_DIM  1024
#define MAX_DIM 4608
#define M_A     (T_STEPS * B_SZ)
#define KSPLIT  8                  // phase-B k-splits (K-chunk 512 = 64 kblocks)
#define A_CHUNK_TILES 8
#define N_CHUNKS (T_STEPS / A_CHUNK_TILES)

// ---------------- scratch (device globals) ---------------------------------
__device__ float g_P[(size_t)M_A * N_RES];
__device__ float g_G[(size_t)M_A * 3 * N_RES];
__device__ float g_state[B_SZ * N_RES];             // exact recurrent state
__device__ float g_stateP[512 * 1024];              // tf32 state, fragment-permuted (2MB)
__device__ float g_part[KSPLIT][B_SZ * N_RES];

__device__ float g_x_r[(size_t)M_A * IN_DIM];
__device__ float g_Win_r[(size_t)N_RES * IN_DIM];
__device__ float g_Wgate_r[(size_t)3 * N_RES * IN_DIM];
__device__ float g_WresP[(size_t)N_RES * N_RES];    // W_res tf32, fragment-permuted

// ---------------- helpers ---------------------------------------------------
__device__ __forceinline__ uint32_t cvt_tf32(float x) {
    uint32_t r;
    asm("cvt.rna.tf32.f32 %0, %1;" : "=r"(r) : "f"(x));
    return r;
}

__device__ __forceinline__ void mma_tf32_16x8x8(float* d, const uint32_t* a, const uint32_t* b) {
    asm volatile(
        "mma.sync.aligned.m16n8k8.row.col.f32.tf32.tf32.f32 "
        "{%0,%1,%2,%3}, {%4,%5,%6,%7}, {%8,%9}, {%0,%1,%2,%3};"
        : "+f"(d[0]), "+f"(d[1]), "+f"(d[2]), "+f"(d[3])
        : "r"(a[0]), "r"(a[1]), "r"(a[2]), "r"(a[3]), "r"(b[0]), "r"(b[1]));
}

__device__ __forceinline__ void cp16(void* sm, const void* gm) {
    uint32_t s = (uint32_t)__cvta_generic_to_shared(sm);
    asm volatile("cp.async.cg.shared.global [%0], [%1], 16;" :: "r"(s), "l"(gm));
}
#define CP_COMMIT() asm volatile("cp.async.commit_group;")
#define CP_WAIT1()  asm volatile("cp.async.wait_group 1;")

// fragment-permuted index for state: value (m, n) -> offset
__device__ __forceinline__ int stateP_idx(int m, int n) {
    const int kblock = n >> 3, tg = n & 3, colhalf = (n >> 2) & 1;
    const int wm = m >> 6, mt = (m >> 4) & 3, rowhalf = (m >> 3) & 1, g = m & 7;
    const int lane = g * 4 + tg;
    const int j = rowhalf + 2 * colhalf;
    return kblock * 1024 + wm * 512 + mt * 128 + lane * 4 + j;
}

// ---------------- pre-rounding ----------------------------------------------
__global__ __launch_bounds__(256) void round4_kernel(const float4* __restrict__ src,
                                                     int n4, int which) {
    float4* dst = (which == 0) ? (float4*)g_x_r
                : (which == 1) ? (float4*)g_Win_r
                               : (float4*)g_Wgate_r;
    int i = blockIdx.x * 256 + threadIdx.x;
    if (i < n4) {
        float4 v = src[i];
        float4 o;
        o.x = __uint_as_float(cvt_tf32(v.x));
        o.y = __uint_as_float(cvt_tf32(v.y));
        o.z = __uint_as_float(cvt_tf32(v.z));
        o.w = __uint_as_float(cvt_tf32(v.w));
        dst[i] = o;
    }
}

// one-time: W_res[k][n] -> tf32, fragment-permuted
// layout: [kblock(512)][n7(32)][wn(4)][khalf(2)][lane(32)][nt(4)]
__global__ __launch_bounds__(256) void permWres_kernel(const float* __restrict__ W) {
    const size_t i = (size_t)blockIdx.x * 256 + threadIdx.x;   // k*4096 + n
    const int k = (int)(i >> 12), n = (int)(i & 4095);
    const float v = W[i];
    const int kblock = k >> 3, ktg = k & 3, khalf = (k >> 2) & 1;
    const int n7 = n >> 7, nl = n & 127;
    const int wn = nl >> 5, nt = (nl >> 3) & 3, g = nl & 7;
    const int lane = g * 4 + ktg;
    const size_t idx = ((((size_t)(kblock * 32 + n7) * 4 + wn) * 2 + khalf) * 32 + lane) * 4 + nt;
    g_WresP[idx] = __uint_as_float(cvt_tf32(v));
}

// ===========================================================================
// Phase A (proven R6 kernel): 256 threads, tile 128x128, warp tile 64x32.
// ===========================================================================
__global__ __launch_bounds__(256) void phaseA_gemm(int tile0) {
    __shared__ uint32_t As[2][128][20];
    __shared__ uint32_t Bs[2][128][20];

    const int tid  = threadIdx.x;
    const int warp = tid >> 5, lane = tid & 31;
    const int g  = lane >> 2, tg = lane & 3;
    const int wm = warp >> 2, wn = warp & 3;
    const int mbase = (tile0 + blockIdx.y) * 128;
    const int fblk  = blockIdx.x;
    const bool isP  = (fblk < 32);
    const float* W  = isP ? g_Win_r : g_Wgate_r;
    const int frow0 = isP ? fblk * 128 : (fblk - 32) * 128;

    float acc[4][4][4];
    #pragma unroll
    for (int i = 0; i < 4; i++)
        #pragma unroll
        for (int j = 0; j < 4; j++)
            #pragma unroll
            for (int c = 0; c < 4; c++) acc[i][j][c] = 0.f;

    const int NIT = IN_DIM / 16;

    auto load_stage = [&](int s, int it) {
        const int k0 = it * 16;
        #pragma unroll
        for (int r = 0; r < 2; r++) {
            int c = tid + r * 256;
            int row = c >> 2, seg = c & 3;
            cp16(&As[s][row][seg * 4], g_x_r + (size_t)(mbase + row) * IN_DIM + k0 + seg * 4);
        }
        #pragma unroll
        for (int r = 0; r < 2; r++) {
            int c = tid + r * 256;
            int row = c >> 2, seg = c & 3;
            cp16(&Bs[s][row][seg * 4], W + (size_t)(frow0 + row) * IN_DIM + k0 + seg * 4);
        }
    };

    load_stage(0, 0);
    CP_COMMIT();

    for (int it = 0; it < NIT; it++) {
        const int s = it & 1;
        if (it + 1 < NIT) load_stage(s ^ 1, it + 1);
        CP_COMMIT();
        CP_WAIT1();
        __syncthreads();

        #pragma unroll
        for (int kk = 0; kk < 16; kk += 8) {
            uint32_t af[4][4], bf[4][2];
            #pragma unroll
            for (int mt = 0; mt < 4; mt++) {
                const int r = wm * 64 + mt * 16 + g;
                af[mt][0] = As[s][r    ][kk + tg    ];
                af[mt][1] = As[s][r + 8][kk + tg    ];
                af[mt][2] = As[s][r    ][kk + tg + 4];
                af[mt][3] = As[s][r + 8][kk + tg + 4];
            }
            #pragma unroll
            for (int nt = 0; nt < 4; nt++) {
                const int fc = wn * 32 + nt * 8 + g;
                bf[nt][0] = Bs[s][fc][kk + tg    ];
                bf[nt][1] = Bs[s][fc][kk + tg + 4];
            }
            #pragma unroll
            for (int mt = 0; mt < 4; mt++)
                #pragma unroll
                for (int nt = 0; nt < 4; nt++)
                    mma_tf32_16x8x8(acc[mt][nt], af[mt], bf[nt]);
        }
        __syncthreads();
    }

    #pragma unroll
    for (int mt = 0; mt < 4; mt++) {
        #pragma unroll
        for (int nt = 0; nt < 4; nt++) {
            const int fc = fblk * 128 + wn * 32 + nt * 8 + 2 * tg;
            #pragma unroll
            for (int half = 0; half < 2; half++) {
                const int m = mbase + wm * 64 + mt * 16 + g + half * 8;
                const float v0 = acc[mt][nt][half * 2 + 0];
                const float v1 = acc[mt][nt][half * 2 + 1];
                if (isP) {
                    *(float2*)&g_P[(size_t)m * N_RES + fc] = make_float2(v0, v1);
                } else {
                    float2 o = make_float2(1.f / (1.f + __expf(-v0)),
                                           1.f / (1.f + __expf(-v1)));
                    *(float2*)&g_G[(size_t)m * (3 * N_RES) + (fc - N_RES)] = o;
                }
            }
        }
    }
}

// ===========================================================================
// Phase B per-step GEMM with fragment-ready operands.
// grid = (32 n-tiles, 8 k-splits) = 256 CTAs, 256 thr, 2 CTAs/SM.
// Per 8-k block each thread does 6 LDS.128 + 16 MMA (was 24 LDS.32 + 16 MMA).
// ===========================================================================
__global__ __launch_bounds__(256, 2) void stepB_gemm() {
    __shared__ float As[2][2048];    // per stage: 2 kblocks x [wm][mt][lane][j]
    __shared__ float Bs[2][2048];    // per stage: 2 kblocks x [wn][khalf][lane][nt]

    const int tid  = threadIdx.x;
    const int warp = tid >> 5, lane = tid & 31;
    const int g  = lane >> 2, tg = lane & 3;
    const int wm = warp >> 2, wn = warp & 3;
    const int n7  = blockIdx.x;                    // 0..31
    const int kb0 = blockIdx.y * 64;               // kblock base (64 kblocks per split)

    float acc[4][4][4];
    #pragma unroll
    for (int i = 0; i < 4; i++)
        #pragma unroll
        for (int j = 0; j < 4; j++)
            #pragma unroll
            for (int c = 0; c < 4; c++) acc[i][j][c] = 0.f;

    const int NIT = 32;   // stages of 2 kblocks (16 k)

    auto load_stage = [&](int s, int it) {
        const int kb = kb0 + it * 2;
        // A: 2 kblocks x 1024 floats, contiguous in g_stateP
        #pragma unroll
        for (int r = 0; r < 2; r++) {
            const int e = tid + r * 256;           // 16B unit 0..511
            cp16(&As[s][e * 4], g_stateP + (size_t)kb * 1024 + e * 4);
        }
        // B: 2 kblocks x 1024 floats at stride 32*1024 in g_WresP
        #pragma unroll
        for (int r = 0; r < 2; r++) {
            const int e = tid + r * 256;           // 0..511
            const int kbl = e >> 8, off = e & 255;
            cp16(&Bs[s][kbl * 1024 + off * 4],
                 g_WresP + ((size_t)(kb + kbl) * 32 + n7) * 1024 + off * 4);
        }
    };

    load_stage(0, 0);
    CP_COMMIT();

    for (int it = 0; it < NIT; it++) {
        const int s = it & 1;
        if (it + 1 < NIT) load_stage(s ^ 1, it + 1);
        CP_COMMIT();
        CP_WAIT1();
        __syncthreads();

        #pragma unroll
        for (int kbl = 0; kbl < 2; kbl++) {
            const float* Ab = &As[s][kbl * 1024 + wm * 512 + lane * 4];
            const float* Bb = &Bs[s][kbl * 1024 + wn * 256 + lane * 4];
            uint32_t af[4][4];
            #pragma unroll
            for (int mt = 0; mt < 4; mt++)
                *(uint4*)af[mt] = *(const uint4*)(Ab + mt * 128);
            uint4 b0 = *(const uint4*)(Bb);          // khalf 0: nt 0..3
            uint4 b1 = *(const uint4*)(Bb + 128);    // khalf 1: nt 0..3
            const uint32_t bn0[4] = {b0.x, b0.y, b0.z, b0.w};
            const uint32_t bn1[4] = {b1.x, b1.y, b1.z, b1.w};
            #pragma unroll
            for (int mt = 0; mt < 4; mt++)
                #pragma unroll
                for (int nt = 0; nt < 4; nt++) {
                    const uint32_t b[2] = {bn0[nt], bn1[nt]};
                    mma_tf32_16x8x8(acc[mt][nt], af[mt], b);
                }
        }
        __syncthreads();
    }

    float* part = g_part[blockIdx.y];
    const int nbase = n7 * 128;
    #pragma unroll
    for (int mt = 0; mt < 4; mt++) {
        #pragma unroll
        for (int nt = 0; nt < 4; nt++) {
            const int n = nbase + wn * 32 + nt * 8 + 2 * tg;
            #pragma unroll
            for (int half = 0; half < 2; half++) {
                const int m = wm * 64 + mt * 16 + g + half * 8;
                *(float2*)&part[(size_t)m * N_RES + n] =
                    make_float2(acc[mt][nt][half * 2 + 0], acc[mt][nt][half * 2 + 1]);
            }
        }
    }
}

// ===========================================================================
// Per-step reduce + cell update; writes exact state, permuted tf32 state, out.
// ===========================================================================
__global__ __launch_bounds__(256) void update_kernel(float* __restrict__ out, int t) {
    const int n = (blockIdx.x * 256 + threadIdx.x) * 4;   // 0..4092 step 4
    const int b = blockIdx.y;
    const int idx = b * N_RES + n;

    float4 res = *(const float4*)&g_part[0][idx];
    #pragma unroll
    for (int ks = 1; ks < KSPLIT; ks++) {
        float4 p = *(const float4*)&g_part[ks][idx];
        res.x += p.x; res.y += p.y; res.z += p.z; res.w += p.w;
    }

    const float4 prev = *(const float4*)&g_state[idx];
    const size_t mrow = (size_t)t * B_SZ + b;
    const float4 pp = *(const float4*)&g_P[mrow * N_RES + n];
    const float* gr = g_G + mrow * (3 * N_RES);
    const float4 gi = *(const float4*)&gr[n];
    const float4 gf = *(const float4*)&gr[N_RES + n];
    const float4 go = *(const float4*)&gr[2 * N_RES + n];

    float4 s;
    s.x = go.x * (0.9f * gf.x * prev.x + 0.1f * tanhf(gi.x * (pp.x + res.x)));
    s.y = go.y * (0.9f * gf.y * prev.y + 0.1f * tanhf(gi.y * (pp.y + res.y)));
    s.z = go.z * (0.9f * gf.z * prev.z + 0.1f * tanhf(gi.z * (pp.z + res.z)));
    s.w = go.w * (0.9f * gf.w * prev.w + 0.1f * tanhf(gi.w * (pp.w + res.w)));
    if (s.x > 0.5f) s.x -= 0.5f;
    if (s.y > 0.5f) s.y -= 0.5f;
    if (s.z > 0.5f) s.z -= 0.5f;
    if (s.w > 0.5f) s.w -= 0.5f;

    *(float4*)&g_state[idx] = s;
    // permuted tf32 state: 4 consecutive n share kblock/colhalf, tg = 0..3
    const int p0 = stateP_idx(b, n);
    g_stateP[p0     ] = __uint_as_float(cvt_tf32(s.x));
    g_stateP[p0 +  4] = __uint_as_float(cvt_tf32(s.y));   // lane+1 -> +4 floats
    g_stateP[p0 +  8] = __uint_as_float(cvt_tf32(s.z));
    g_stateP[p0 + 12] = __uint_as_float(cvt_tf32(s.w));
    *(float4*)&out[mrow * MAX_DIM + n] = s;
}

// ---------------- init / padding ------------------------------------------
__global__ __launch_bounds__(256) void init_state_kernel(const float* __restrict__ state0) {
    const int n = blockIdx.x * 256 + threadIdx.x;
    const int b = blockIdx.y;
    const float v = state0[(size_t)b * MAX_DIM + n];
    g_state[b * N_RES + n] = v;
    g_stateP[stateP_idx(b, n)] = __uint_as_float(cvt_tf32(v));
}

__global__ __launch_bounds__(256) void pad_out_kernel(float4* __restrict__ out) {
    const int idx = blockIdx.x * 256 + threadIdx.x;
    const int tb = idx >> 7;
    const int c = idx & 127;
    out[(size_t)tb * (MAX_DIM / 4) + (N_RES / 4) + c] = make_float4(0.f, 0.f, 0.f, 0.f);
}

// ===========================================================================
extern "C" void kernel_launch(void* const* d_in, const int* in_sizes, int n_in,
                              void* d_out, int out_size) {
    const float* x      = (const float*)d_in[0];
    const float* state0 = (const float*)d_in[1];
    const float* W_res  = (const float*)d_in[2];
    const float* W_in   = (const float*)d_in[3];
    const float* W_gate = (const float*)d_in[4];
    float* out = (float*)d_out;

    static cudaStream_t s2 = nullptr;
    static cudaEvent_t evFork = nullptr;
    static cudaEvent_t evChunk[N_CHUNKS];
    static bool setup_tried = false;
    static bool overlap_ok = false;
    if (!setup_tried) {
        setup_tried = true;
        cudaStreamCaptureStatus cap = cudaStreamCaptureStatusNone;
        cudaStreamIsCapturing(0, &cap);
        if (cap == cudaStreamCaptureStatusNone) {
            bool ok = (cudaStreamCreateWithFlags(&s2, cudaStreamNonBlocking) == cudaSuccess);
            ok = ok && (cudaEventCreateWithFlags(&evFork, cudaEventDisableTiming) == cudaSuccess);
            for (int c = 0; ok && c < N_CHUNKS; c++)
                ok = (cudaEventCreateWithFlags(&evChunk[c], cudaEventDisableTiming) == cudaSuccess);
            overlap_ok = ok;
        }
    }

    // ---- operand prep ------------------------------------------------------
    round4_kernel<<<16384, 256>>>((const float4*)x,      (M_A * IN_DIM) / 4,       0);
    round4_kernel<<< 4096, 256>>>((const float4*)W_in,   (N_RES * IN_DIM) / 4,     1);
    round4_kernel<<<12288, 256>>>((const float4*)W_gate, (3 * N_RES * IN_DIM) / 4, 2);
    permWres_kernel<<<65536, 256>>>(W_res);
    init_state_kernel<<<dim3(16, 128), 256>>>(state0);
    pad_out_kernel<<<8192, 256>>>((float4*)out);

    if (overlap_ok) {
        cudaEventRecord(evFork, 0);
        cudaStreamWaitEvent(s2, evFork, 0);
        for (int c = 0; c < N_CHUNKS; c++) {
            phaseA_gemm<<<dim3(128, A_CHUNK_TILES), 256, 0, s2>>>(c * A_CHUNK_TILES);
            cudaEventRecord(evChunk[c], s2);
        }
        for (int t = 0; t < T_STEPS; t++) {
            stepB_gemm<<<dim3(32, KSPLIT), 256>>>();
            if ((t % A_CHUNK_TILES) == 0)
                cudaStreamWaitEvent(0, evChunk[t / A_CHUNK_TILES], 0);
            update_kernel<<<dim3(4, 128), 256>>>(out, t);
        }
    } else {
        for (int c = 0; c < N_CHUNKS; c++)
            phaseA_gemm<<<dim3(128, A_CHUNK_TILES), 256>>>(c * A_CHUNK_TILES);
        for (int t = 0; t < T_STEPS; t++) {
            stepB_gemm<<<dim3(32, KSPLIT), 256>>>();
            update_kernel<<<dim3(4, 128), 256>>>(out, t);
        }
    }
}

// round 13
// speedup vs baseline: 1.4883x; 1.1407x over previous
#include <cuda_runtime.h>
#include <cstdint>

#define T_STEPS 128
#define B_SZ    128
#define N_RES   4096
#define IN_DIM  1024
#define MAX_DIM 4608
#define M_A     (T_STEPS * B_SZ)
#define KSPLIT  8                  // phase-B k-splits (64 kblocks per split)
#define A_CHUNK_TILES 8
#define N_CHUNKS (T_STEPS / A_CHUNK_TILES)

// 3-stage x 4-kblock pipeline (shared by both GEMMs)
#define KB_PER_STAGE 4
#define STAGE_FLOATS 8192              // 4kb x 1024 A + 4kb x 1024 B
#define DSMEM_BYTES  (3 * STAGE_FLOATS * 4)   // 98304

// ---------------- scratch (device globals) ---------------------------------
__device__ float g_P[(size_t)M_A * N_RES];
__device__ float g_G[(size_t)M_A * 3 * N_RES];
__device__ float g_state[B_SZ * N_RES];             // exact recurrent state
__device__ float g_stateP[512 * 1024];              // tf32 state, fragment-permuted
__device__ float g_part[KSPLIT][B_SZ * N_RES];

__device__ float g_xP[(size_t)M_A * IN_DIM];        // x tf32, fragment-permuted (A)
__device__ float g_WabP[(size_t)(4 * N_RES) * IN_DIM]; // W_in++W_gate tf32, permuted (B)
__device__ float g_WresP[(size_t)N_RES * N_RES];    // W_res tf32, fragment-permuted (B)

// ---------------- helpers ---------------------------------------------------
__device__ __forceinline__ uint32_t cvt_tf32(float x) {
    uint32_t r;
    asm("cvt.rna.tf32.f32 %0, %1;" : "=r"(r) : "f"(x));
    return r;
}

__device__ __forceinline__ void mma_tf32_16x8x8(float* d, const uint32_t* a, const uint32_t* b) {
    asm volatile(
        "mma.sync.aligned.m16n8k8.row.col.f32.tf32.tf32.f32 "
        "{%0,%1,%2,%3}, {%4,%5,%6,%7}, {%8,%9}, {%0,%1,%2,%3};"
        : "+f"(d[0]), "+f"(d[1]), "+f"(d[2]), "+f"(d[3])
        : "r"(a[0]), "r"(a[1]), "r"(a[2]), "r"(a[3]), "r"(b[0]), "r"(b[1]));
}

__device__ __forceinline__ void cp16(void* sm, const void* gm) {
    uint32_t s = (uint32_t)__cvta_generic_to_shared(sm);
    asm volatile("cp.async.cg.shared.global [%0], [%1], 16;" :: "r"(s), "l"(gm));
}
#define CP_COMMIT() asm volatile("cp.async.commit_group;")
#define CP_WAIT1()  asm volatile("cp.async.wait_group 1;")

// fragment-permuted A index (verified in R11): (m in [0,128), k) -> offset
__device__ __forceinline__ int fragA_idx(int m, int k) {
    const int kblock = k >> 3, tg = k & 3, colhalf = (k >> 2) & 1;
    const int wm = m >> 6, mt = (m >> 4) & 3, rowhalf = (m >> 3) & 1, g = m & 7;
    return kblock * 1024 + wm * 512 + mt * 128 + (g * 4 + tg) * 4 + (rowhalf + 2 * colhalf);
}

// ---------------- operand permutation kernels -------------------------------
// x[m][k] (m<16384, k<1024) -> g_xP, per 128-row m-tile, fragment layout
__global__ __launch_bounds__(256) void permX_kernel(const float* __restrict__ X) {
    const size_t i = (size_t)blockIdx.x * 256 + threadIdx.x;   // m*1024 + k
    const int m = (int)(i >> 10), k = (int)(i & 1023);
    const float v = X[i];
    const int mtile = m >> 7, mloc = m & 127;
    g_xP[(size_t)mtile * 131072 + fragA_idx(mloc, k)] = __uint_as_float(cvt_tf32(v));
}

// W[f][k] (k<1024) -> g_WabP fragment layout (f plays the "n" role).
// layout: [kblock(128)][n7(128)][wn(4)][khalf(2)][lane(32)][nt(4)]
__global__ __launch_bounds__(256) void permWab_kernel(const float* __restrict__ W,
                                                      int nf, int f_off) {
    const size_t i = (size_t)blockIdx.x * 256 + threadIdx.x;   // f*1024 + k
    if (i >= (size_t)nf * IN_DIM) return;
    const int f = (int)(i >> 10), k = (int)(i & 1023);
    const float v = W[i];
    const int fg = f + f_off;
    const int kblock = k >> 3, ktg = k & 3, khalf = (k >> 2) & 1;
    const int n7 = fg >> 7, nl = fg & 127;
    const int wn = nl >> 5, nt = (nl >> 3) & 3, g = nl & 7;
    const size_t idx = ((((size_t)(kblock * 128 + n7) * 4 + wn) * 2 + khalf) * 32
                        + (g * 4 + ktg)) * 4 + nt;
    g_WabP[idx] = __uint_as_float(cvt_tf32(v));
}

// W_res[k][n] -> g_WresP (verified in R11)
// layout: [kblock(512)][n7(32)][wn(4)][khalf(2)][lane(32)][nt(4)]
__global__ __launch_bounds__(256) void permWres_kernel(const float* __restrict__ W) {
    const size_t i = (size_t)blockIdx.x * 256 + threadIdx.x;   // k*4096 + n
    const int k = (int)(i >> 12), n = (int)(i & 4095);
    const float v = W[i];
    const int kblock = k >> 3, ktg = k & 3, khalf = (k >> 2) & 1;
    const int n7 = n >> 7, nl = n & 127;
    const int wn = nl >> 5, nt = (nl >> 3) & 3, g = nl & 7;
    const size_t idx = ((((size_t)(kblock * 32 + n7) * 4 + wn) * 2 + khalf) * 32
                        + (g * 4 + ktg)) * 4 + nt;
    g_WresP[idx] = __uint_as_float(cvt_tf32(v));
}

// ===========================================================================
// Shared fragment-GEMM mainloop body (A/B already fragment-ordered in smem).
// Stage layout in dynamic smem: A at s*8192, B at s*8192+4096 (floats).
// ===========================================================================
#define GEMM_COMPUTE_STAGE(sm, s)                                              \
    do {                                                                       \
        _Pragma("unroll")                                                      \
        for (int kbl = 0; kbl < KB_PER_STAGE; kbl++) {                         \
            const float* Ab = (sm) + (s) * STAGE_FLOATS + kbl * 1024           \
                              + wm * 512 + lane * 4;                           \
            const float* Bb = (sm) + (s) * STAGE_FLOATS + 4096 + kbl * 1024    \
                              + wn * 256 + lane * 4;                           \
            uint32_t af[4][4];                                                 \
            _Pragma("unroll")                                                  \
            for (int mt = 0; mt < 4; mt++)                                     \
                *(uint4*)af[mt] = *(const uint4*)(Ab + mt * 128);              \
            uint4 b0 = *(const uint4*)(Bb);                                    \
            uint4 b1 = *(const uint4*)(Bb + 128);                              \
            const uint32_t bn0[4] = {b0.x, b0.y, b0.z, b0.w};                  \
            const uint32_t bn1[4] = {b1.x, b1.y, b1.z, b1.w};                  \
            _Pragma("unroll")                                                  \
            for (int mt = 0; mt < 4; mt++)                                     \
                _Pragma("unroll")                                              \
                for (int nt = 0; nt < 4; nt++) {                               \
                    const uint32_t b[2] = {bn0[nt], bn1[nt]};                  \
                    mma_tf32_16x8x8(acc[mt][nt], af[mt], b);                   \
                }                                                              \
        }                                                                      \
    } while (0)

// ===========================================================================
// Phase A fragment GEMM: grid (128 n7, A_CHUNK_TILES m-tiles), 256 thr.
// K = 1024 = 128 kblocks, 32 stages of 4.
// ===========================================================================
__global__ __launch_bounds__(256, 2) void phaseA_frag(int tile0) {
    extern __shared__ float sm[];
    const int tid  = threadIdx.x;
    const int warp = tid >> 5, lane = tid & 31;
    const int g  = lane >> 2, tg = lane & 3;
    const int wm = warp >> 2, wn = warp & 3;
    const int n7    = blockIdx.x;                       // 0..127
    const int mtile = tile0 + blockIdx.y;
    const float* Asrc = g_xP + (size_t)mtile * 131072;

    float acc[4][4][4];
    #pragma unroll
    for (int i = 0; i < 4; i++)
        #pragma unroll
        for (int j = 0; j < 4; j++)
            #pragma unroll
            for (int c = 0; c < 4; c++) acc[i][j][c] = 0.f;

    const int NIT = 32;

    auto load_stage = [&](int s, int it) {
        const int kb = it * KB_PER_STAGE;
        #pragma unroll
        for (int r = 0; r < 4; r++) {                   // A: 1024 x 16B units
            const int e = tid + r * 256;
            cp16(sm + s * STAGE_FLOATS + e * 4, Asrc + (size_t)kb * 1024 + e * 4);
        }
        #pragma unroll
        for (int r = 0; r < 4; r++) {                   // B: 1024 x 16B units
            const int e = tid + r * 256;
            const int kbl = e >> 8, off = e & 255;
            cp16(sm + s * STAGE_FLOATS + 4096 + kbl * 1024 + off * 4,
                 g_WabP + ((size_t)(kb + kbl) * 128 + n7) * 1024 + off * 4);
        }
    };

    load_stage(0, 0); CP_COMMIT();
    load_stage(1, 1); CP_COMMIT();

    for (int it = 0; it < NIT; it++) {
        const int s = it % 3;
        CP_WAIT1();
        __syncthreads();
        if (it + 2 < NIT) { load_stage((it + 2) % 3, it + 2); CP_COMMIT(); }
        GEMM_COMPUTE_STAGE(sm, s);
    }

    // epilogue: fc in [0,16384); <4096 -> P raw, else -> G sigmoid
    const bool isP = (n7 < 32);
    #pragma unroll
    for (int mt = 0; mt < 4; mt++) {
        #pragma unroll
        for (int nt = 0; nt < 4; nt++) {
            const int fc = n7 * 128 + wn * 32 + nt * 8 + 2 * tg;
            #pragma unroll
            for (int half = 0; half < 2; half++) {
                const int m = mtile * 128 + wm * 64 + mt * 16 + g + half * 8;
                const float v0 = acc[mt][nt][half * 2 + 0];
                const float v1 = acc[mt][nt][half * 2 + 1];
                if (isP) {
                    *(float2*)&g_P[(size_t)m * N_RES + fc] = make_float2(v0, v1);
                } else {
                    float2 o = make_float2(1.f / (1.f + __expf(-v0)),
                                           1.f / (1.f + __expf(-v1)));
                    *(float2*)&g_G[(size_t)m * (3 * N_RES) + (fc - N_RES)] = o;
                }
            }
        }
    }
}

// ===========================================================================
// Phase B fragment GEMM: grid (32 n7, 8 ksplits), 256 thr, 16 stages of 4 kb.
// ===========================================================================
__global__ __launch_bounds__(256, 2) void stepB_gemm() {
    extern __shared__ float sm[];
    const int tid  = threadIdx.x;
    const int warp = tid >> 5, lane = tid & 31;
    const int g  = lane >> 2, tg = lane & 3;
    const int wm = warp >> 2, wn = warp & 3;
    const int n7  = blockIdx.x;                         // 0..31
    const int kb0 = blockIdx.y * 64;                    // kblock base

    float acc[4][4][4];
    #pragma unroll
    for (int i = 0; i < 4; i++)
        #pragma unroll
        for (int j = 0; j < 4; j++)
            #pragma unroll
            for (int c = 0; c < 4; c++) acc[i][j][c] = 0.f;

    const int NIT = 16;

    auto load_stage = [&](int s, int it) {
        const int kb = kb0 + it * KB_PER_STAGE;
        #pragma unroll
        for (int r = 0; r < 4; r++) {                   // A
            const int e = tid + r * 256;
            cp16(sm + s * STAGE_FLOATS + e * 4, g_stateP + (size_t)kb * 1024 + e * 4);
        }
        #pragma unroll
        for (int r = 0; r < 4; r++) {                   // B
            const int e = tid + r * 256;
            const int kbl = e >> 8, off = e & 255;
            cp16(sm + s * STAGE_FLOATS + 4096 + kbl * 1024 + off * 4,
                 g_WresP + ((size_t)(kb + kbl) * 32 + n7) * 1024 + off * 4);
        }
    };

    load_stage(0, 0); CP_COMMIT();
    load_stage(1, 1); CP_COMMIT();

    for (int it = 0; it < NIT; it++) {
        const int s = it % 3;
        CP_WAIT1();
        __syncthreads();
        if (it + 2 < NIT) { load_stage((it + 2) % 3, it + 2); CP_COMMIT(); }
        GEMM_COMPUTE_STAGE(sm, s);
    }

    float* part = g_part[blockIdx.y];
    const int nbase = n7 * 128;
    #pragma unroll
    for (int mt = 0; mt < 4; mt++) {
        #pragma unroll
        for (int nt = 0; nt < 4; nt++) {
            const int n = nbase + wn * 32 + nt * 8 + 2 * tg;
            #pragma unroll
            for (int half = 0; half < 2; half++) {
                const int m = wm * 64 + mt * 16 + g + half * 8;
                *(float2*)&part[(size_t)m * N_RES + n] =
                    make_float2(acc[mt][nt][half * 2 + 0], acc[mt][nt][half * 2 + 1]);
            }
        }
    }
}

// ===========================================================================
// Per-step reduce + cell update; writes exact state, permuted tf32 state, out.
// ===========================================================================
__global__ __launch_bounds__(256) void update_kernel(float* __restrict__ out, int t) {
    const int n = (blockIdx.x * 256 + threadIdx.x) * 4;
    const int b = blockIdx.y;
    const int idx = b * N_RES + n;

    float4 res = *(const float4*)&g_part[0][idx];
    #pragma unroll
    for (int ks = 1; ks < KSPLIT; ks++) {
        float4 p = *(const float4*)&g_part[ks][idx];
        res.x += p.x; res.y += p.y; res.z += p.z; res.w += p.w;
    }

    const float4 prev = *(const float4*)&g_state[idx];
    const size_t mrow = (size_t)t * B_SZ + b;
    const float4 pp = *(const float4*)&g_P[mrow * N_RES + n];
    const float* gr = g_G + mrow * (3 * N_RES);
    const float4 gi = *(const float4*)&gr[n];
    const float4 gf = *(const float4*)&gr[N_RES + n];
    const float4 go = *(const float4*)&gr[2 * N_RES + n];

    float4 s;
    s.x = go.x * (0.9f * gf.x * prev.x + 0.1f * tanhf(gi.x * (pp.x + res.x)));
    s.y = go.y * (0.9f * gf.y * prev.y + 0.1f * tanhf(gi.y * (pp.y + res.y)));
    s.z = go.z * (0.9f * gf.z * prev.z + 0.1f * tanhf(gi.z * (pp.z + res.z)));
    s.w = go.w * (0.9f * gf.w * prev.w + 0.1f * tanhf(gi.w * (pp.w + res.w)));
    if (s.x > 0.5f) s.x -= 0.5f;
    if (s.y > 0.5f) s.y -= 0.5f;
    if (s.z > 0.5f) s.z -= 0.5f;
    if (s.w > 0.5f) s.w -= 0.5f;

    *(float4*)&g_state[idx] = s;
    const int p0 = fragA_idx(b, n);       // n%4==0: lane walks +4 floats per n
    g_stateP[p0     ] = __uint_as_float(cvt_tf32(s.x));
    g_stateP[p0 +  4] = __uint_as_float(cvt_tf32(s.y));
    g_stateP[p0 +  8] = __uint_as_float(cvt_tf32(s.z));
    g_stateP[p0 + 12] = __uint_as_float(cvt_tf32(s.w));
    *(float4*)&out[mrow * MAX_DIM + n] = s;
}

// ---------------- init / padding ------------------------------------------
__global__ __launch_bounds__(256) void init_state_kernel(const float* __restrict__ state0) {
    const int n = blockIdx.x * 256 + threadIdx.x;
    const int b = blockIdx.y;
    const float v = state0[(size_t)b * MAX_DIM + n];
    g_state[b * N_RES + n] = v;
    g_stateP[fragA_idx(b, n)] = __uint_as_float(cvt_tf32(v));
}

__global__ __launch_bounds__(256) void pad_out_kernel(float4* __restrict__ out) {
    const int idx = blockIdx.x * 256 + threadIdx.x;
    const int tb = idx >> 7;
    const int c = idx & 127;
    out[(size_t)tb * (MAX_DIM / 4) + (N_RES / 4) + c] = make_float4(0.f, 0.f, 0.f, 0.f);
}

// ===========================================================================
extern "C" void kernel_launch(void* const* d_in, const int* in_sizes, int n_in,
                              void* d_out, int out_size) {
    const float* x      = (const float*)d_in[0];
    const float* state0 = (const float*)d_in[1];
    const float* W_res  = (const float*)d_in[2];
    const float* W_in   = (const float*)d_in[3];
    const float* W_gate = (const float*)d_in[4];
    float* out = (float*)d_out;

    static cudaStream_t s2 = nullptr;
    static cudaEvent_t evFork = nullptr;
    static cudaEvent_t evChunk[N_CHUNKS];
    static bool setup_tried = false;
    static bool overlap_ok = false;
    if (!setup_tried) {
        setup_tried = true;
        cudaFuncSetAttribute(phaseA_frag, cudaFuncAttributeMaxDynamicSharedMemorySize,
                             DSMEM_BYTES);
        cudaFuncSetAttribute(stepB_gemm, cudaFuncAttributeMaxDynamicSharedMemorySize,
                             DSMEM_BYTES);
        cudaStreamCaptureStatus cap = cudaStreamCaptureStatusNone;
        cudaStreamIsCapturing(0, &cap);
        if (cap == cudaStreamCaptureStatusNone) {
            bool ok = (cudaStreamCreateWithFlags(&s2, cudaStreamNonBlocking) == cudaSuccess);
            ok = ok && (cudaEventCreateWithFlags(&evFork, cudaEventDisableTiming) == cudaSuccess);
            for (int c = 0; ok && c < N_CHUNKS; c++)
                ok = (cudaEventCreateWithFlags(&evChunk[c], cudaEventDisableTiming) == cudaSuccess);
            overlap_ok = ok;
        }
    }

    // ---- operand prep (all fragment-permuted + tf32-rounded) ---------------
    permX_kernel<<<65536, 256>>>(x);
    permWab_kernel<<<16384, 256>>>(W_in,   N_RES,     0);
    permWab_kernel<<<49152, 256>>>(W_gate, 3 * N_RES, N_RES);
    permWres_kernel<<<65536, 256>>>(W_res);
    init_state_kernel<<<dim3(16, 128), 256>>>(state0);
    pad_out_kernel<<<8192, 256>>>((float4*)out);

    if (overlap_ok) {
        cudaEventRecord(evFork, 0);
        cudaStreamWaitEvent(s2, evFork, 0);
        for (int c = 0; c < N_CHUNKS; c++) {
            phaseA_frag<<<dim3(128, A_CHUNK_TILES), 256, DSMEM_BYTES, s2>>>(c * A_CHUNK_TILES);
            cudaEventRecord(evChunk[c], s2);
        }
        for (int t = 0; t < T_STEPS; t++) {
            stepB_gemm<<<dim3(32, KSPLIT), 256, DSMEM_BYTES>>>();
            if ((t % A_CHUNK_TILES) == 0)
                cudaStreamWaitEvent(0, evChunk[t / A_CHUNK_TILES], 0);
            update_kernel<<<dim3(4, 128), 256>>>(out, t);
        }
    } else {
        for (int c = 0; c < N_CHUNKS; c++)
            phaseA_frag<<<dim3(128, A_CHUNK_TILES), 256, DSMEM_BYTES>>>(c * A_CHUNK_TILES);
        for (int t = 0; t < T_STEPS; t++) {
            stepB_gemm<<<dim3(32, KSPLIT), 256, DSMEM_BYTES>>>();
            update_kernel<<<dim3(4, 128), 256>>>(out, t);
        }
    }
}

// round 15
// speedup vs baseline: 2.6077x; 1.7521x over previous
#include <cuda_runtime.h>
#include <cuda_fp16.h>
#include <cstdint>

#define T_STEPS 128
#define B_SZ    128
#define N_RES   4096
#define IN_DIM  1024
#define MAX_DIM 4608
#define M_A     (T_STEPS * B_SZ)
#define KSPLIT  8                  // phase-B k-splits (32 kblocks of 16k per split)
#define A_CHUNK_TILES 8
#define N_CHUNKS (T_STEPS / A_CHUNK_TILES)   // 16

// 3-stage x 4-kblock pipeline; kblock = 16 k of fp16 = 1024 uint32 per operand
#define KB_PER_STAGE 4
#define STAGE_U32   8192               // 4kb x 1024 A + 4kb x 1024 B (uint32)
#define DSMEM_BYTES (3 * STAGE_U32 * 4)   // 98304

// ---------------- scratch (device globals) ---------------------------------
__device__ float g_P[(size_t)M_A * N_RES];
__device__ float g_G[(size_t)M_A * 3 * N_RES];
__device__ float g_state[B_SZ * N_RES];              // exact recurrent state
__device__ uint32_t g_stateP[256 * 1024];            // fp16x2 state, fragment-permuted
__device__ float g_part[KSPLIT][B_SZ * N_RES];

__device__ uint32_t g_xP[(size_t)M_A * IN_DIM / 2];          // x fp16, permuted (A)
__device__ uint32_t g_WabP[(size_t)4 * N_RES * IN_DIM / 2];  // W_in++W_gate fp16 (B)
__device__ uint32_t g_WresP[(size_t)N_RES * N_RES / 2];      // W_res fp16 (B)

// ---------------- helpers ---------------------------------------------------
__device__ __forceinline__ uint32_t packh2(float lo, float hi) {
    __half2 h = __floats2half2_rn(lo, hi);
    return *reinterpret_cast<uint32_t*>(&h);
}

__device__ __forceinline__ void mma_f16_16x8x16(float* d, const uint32_t* a,
                                                const uint32_t* b) {
    asm volatile(
        "mma.sync.aligned.m16n8k16.row.col.f32.f16.f16.f32 "
        "{%0,%1,%2,%3}, {%4,%5,%6,%7}, {%8,%9}, {%0,%1,%2,%3};"
        : "+f"(d[0]), "+f"(d[1]), "+f"(d[2]), "+f"(d[3])
        : "r"(a[0]), "r"(a[1]), "r"(a[2]), "r"(a[3]), "r"(b[0]), "r"(b[1]));
}

__device__ __forceinline__ void cp16(void* sm, const void* gm) {
    uint32_t s = (uint32_t)__cvta_generic_to_shared(sm);
    asm volatile("cp.async.cg.shared.global [%0], [%1], 16;" :: "r"(s), "l"(gm));
}
#define CP_COMMIT() asm volatile("cp.async.commit_group;")
#define CP_WAIT1()  asm volatile("cp.async.wait_group 1;")

// uint32 index of the half2 holding (k, k+1) for A-operand element (m, k even).
// m16n8k16 A fragment: a_j at lane g*4+tg holds rows {g, g+8}, k {2tg,2tg+1,+8}.
__device__ __forceinline__ int fragAH_idx(int m, int k) {
    const int kblock = k >> 4, tg = (k >> 1) & 3, khalf = (k >> 3) & 1;
    const int wm = m >> 6, mt = (m >> 4) & 3, rowhalf = (m >> 3) & 1, g = m & 7;
    return kblock * 1024 + wm * 512 + mt * 128 + (g * 4 + tg) * 4 + (rowhalf + 2 * khalf);
}

// ---------------- operand permutation kernels -------------------------------
// x[m][k] -> g_xP: per 128-row m-tile, fp16 fragment layout (pairs along k)
__global__ __launch_bounds__(256) void permX_kernel(const float* __restrict__ X) {
    const size_t i = (size_t)blockIdx.x * 256 + threadIdx.x;   // m*512 + kpair
    const int m = (int)(i >> 9), k = (int)(i & 511) * 2;
    const float2 v = *(const float2*)&X[(size_t)m * IN_DIM + k];
    const int mtile = m >> 7, mloc = m & 127;
    g_xP[(size_t)mtile * 65536 + fragAH_idx(mloc, k)] = packh2(v.x, v.y);
}

// W[f][k] -> g_WabP (f plays n). layout: [kblock(64)][n7(128)][wn][khalf][lane][nt]
__global__ __launch_bounds__(256) void permWab_kernel(const float* __restrict__ W,
                                                      int nf, int f_off) {
    const size_t i = (size_t)blockIdx.x * 256 + threadIdx.x;   // f*512 + kpair
    if (i >= (size_t)nf * (IN_DIM / 2)) return;
    const int f = (int)(i >> 9), k = (int)(i & 511) * 2;
    const float2 v = *(const float2*)&W[(size_t)f * IN_DIM + k];
    const int fg = f + f_off;
    const int kblock = k >> 4, tg = (k >> 1) & 3, khalf = (k >> 3) & 1;
    const int n7 = fg >> 7, nl = fg & 127;
    const int wn = nl >> 5, nt = (nl >> 3) & 3, g = nl & 7;
    const size_t idx = (size_t)(kblock * 128 + n7) * 1024
                     + wn * 256 + khalf * 128 + (g * 4 + tg) * 4 + nt;
    g_WabP[idx] = packh2(v.x, v.y);
}

// W_res[k][n] -> g_WresP. layout: [kblock(256)][n7(32)][wn][khalf][lane][nt]
__global__ __launch_bounds__(256) void permWres_kernel(const float* __restrict__ W) {
    const size_t i = (size_t)blockIdx.x * 256 + threadIdx.x;   // kpair*4096 + n
    const int k = (int)(i >> 12) * 2, n = (int)(i & 4095);
    const float lo = W[(size_t)k * N_RES + n];
    const float hi = W[(size_t)(k + 1) * N_RES + n];
    const int kblock = k >> 4, tg = (k >> 1) & 3, khalf = (k >> 3) & 1;
    const int n7 = n >> 7, nl = n & 127;
    const int wn = nl >> 5, nt = (nl >> 3) & 3, g = nl & 7;
    const size_t idx = (size_t)(kblock * 32 + n7) * 1024
                     + wn * 256 + khalf * 128 + (g * 4 + tg) * 4 + nt;
    g_WresP[idx] = packh2(lo, hi);
}

// ===========================================================================
// Shared fragment-GEMM mainloop body (fp16; smem already fragment-ordered).
// Stage layout in dynamic smem (uint32): A at s*8192, B at s*8192+4096.
// ===========================================================================
#define GEMM_COMPUTE_STAGE(smp, s)                                             \
    do {                                                                       \
        _Pragma("unroll")                                                      \
        for (int kbl = 0; kbl < KB_PER_STAGE; kbl++) {                         \
            const uint32_t* Ab = (smp) + (s) * STAGE_U32 + kbl * 1024          \
                                 + wm * 512 + lane * 4;                        \
            const uint32_t* Bb = (smp) + (s) * STAGE_U32 + 4096 + kbl * 1024   \
                                 + wn * 256 + lane * 4;                        \
            uint32_t af[4][4];                                                 \
            _Pragma("unroll")                                                  \
            for (int mt = 0; mt < 4; mt++)                                     \
                *(uint4*)af[mt] = *(const uint4*)(Ab + mt * 128);              \
            uint4 b0 = *(const uint4*)(Bb);                                    \
            uint4 b1 = *(const uint4*)(Bb + 128);                              \
            const uint32_t bn0[4] = {b0.x, b0.y, b0.z, b0.w};                  \
            const uint32_t bn1[4] = {b1.x, b1.y, b1.z, b1.w};                  \
            _Pragma("unroll")                                                  \
            for (int mt = 0; mt < 4; mt++)                                     \
                _Pragma("unroll")                                              \
                for (int nt = 0; nt < 4; nt++) {                               \
                    const uint32_t b[2] = {bn0[nt], bn1[nt]};                  \
                    mma_f16_16x8x16(acc[mt][nt], af[mt], b);                   \
                }                                                              \
        }                                                                      \
    } while (0)

// ===========================================================================
// Phase A fragment GEMM: grid (128 n7, A_CHUNK_TILES m-tiles), 256 thr.
// K = 1024 = 64 kblocks = 16 stages of 4.
// ===========================================================================
__global__ __launch_bounds__(256, 2) void phaseA_frag(int tile0) {
    extern __shared__ uint32_t smp[];
    const int tid  = threadIdx.x;
    const int warp = tid >> 5, lane = tid & 31;
    const int g  = lane >> 2, tg = lane & 3;
    const int wm = warp >> 2, wn = warp & 3;
    const int n7    = blockIdx.x;                       // 0..127
    const int mtile = tile0 + blockIdx.y;
    const uint32_t* Asrc = g_xP + (size_t)mtile * 65536;

    float acc[4][4][4];
    #pragma unroll
    for (int i = 0; i < 4; i++)
        #pragma unroll
        for (int j = 0; j < 4; j++)
            #pragma unroll
            for (int c = 0; c < 4; c++) acc[i][j][c] = 0.f;

    const int NIT = 16;

    auto load_stage = [&](int s, int it) {
        const int kb = it * KB_PER_STAGE;
        #pragma unroll
        for (int r = 0; r < 4; r++) {                   // A: 1024 x 16B units
            const int e = tid + r * 256;
            cp16(smp + s * STAGE_U32 + e * 4, Asrc + (size_t)kb * 1024 + e * 4);
        }
        #pragma unroll
        for (int r = 0; r < 4; r++) {                   // B
            const int e = tid + r * 256;
            const int kbl = e >> 8, off = e & 255;
            cp16(smp + s * STAGE_U32 + 4096 + kbl * 1024 + off * 4,
                 g_WabP + ((size_t)(kb + kbl) * 128 + n7) * 1024 + off * 4);
        }
    };

    load_stage(0, 0); CP_COMMIT();
    load_stage(1, 1); CP_COMMIT();

    for (int it = 0; it < NIT; it++) {
        const int s = it % 3;
        CP_WAIT1();
        __syncthreads();
        if (it + 2 < NIT) { load_stage((it + 2) % 3, it + 2); CP_COMMIT(); }
        GEMM_COMPUTE_STAGE(smp, s);
    }

    const bool isP = (n7 < 32);
    #pragma unroll
    for (int mt = 0; mt < 4; mt++) {
        #pragma unroll
        for (int nt = 0; nt < 4; nt++) {
            const int fc = n7 * 128 + wn * 32 + nt * 8 + 2 * tg;
            #pragma unroll
            for (int half = 0; half < 2; half++) {
                const int m = mtile * 128 + wm * 64 + mt * 16 + g + half * 8;
                const float v0 = acc[mt][nt][half * 2 + 0];
                const float v1 = acc[mt][nt][half * 2 + 1];
                if (isP) {
                    *(float2*)&g_P[(size_t)m * N_RES + fc] = make_float2(v0, v1);
                } else {
                    float2 o = make_float2(1.f / (1.f + __expf(-v0)),
                                           1.f / (1.f + __expf(-v1)));
                    *(float2*)&g_G[(size_t)m * (3 * N_RES) + (fc - N_RES)] = o;
                }
            }
        }
    }
}

// ===========================================================================
// Phase B fragment GEMM: grid (32 n7, 8 ksplits), 256 thr, 8 stages of 4 kb.
// ===========================================================================
__global__ __launch_bounds__(256, 2) void stepB_gemm() {
    extern __shared__ uint32_t smp[];
    const int tid  = threadIdx.x;
    const int warp = tid >> 5, lane = tid & 31;
    const int g  = lane >> 2, tg = lane & 3;
    const int wm = warp >> 2, wn = warp & 3;
    const int n7  = blockIdx.x;                         // 0..31
    const int kb0 = blockIdx.y * 32;                    // kblock base (16k each)

    float acc[4][4][4];
    #pragma unroll
    for (int i = 0; i < 4; i++)
        #pragma unroll
        for (int j = 0; j < 4; j++)
            #pragma unroll
            for (int c = 0; c < 4; c++) acc[i][j][c] = 0.f;

    const int NIT = 8;

    auto load_stage = [&](int s, int it) {
        const int kb = kb0 + it * KB_PER_STAGE;
        #pragma unroll
        for (int r = 0; r < 4; r++) {                   // A
            const int e = tid + r * 256;
            cp16(smp + s * STAGE_U32 + e * 4, g_stateP + (size_t)kb * 1024 + e * 4);
        }
        #pragma unroll
        for (int r = 0; r < 4; r++) {                   // B
            const int e = tid + r * 256;
            const int kbl = e >> 8, off = e & 255;
            cp16(smp + s * STAGE_U32 + 4096 + kbl * 1024 + off * 4,
                 g_WresP + ((size_t)(kb + kbl) * 32 + n7) * 1024 + off * 4);
        }
    };

    load_stage(0, 0); CP_COMMIT();
    load_stage(1, 1); CP_COMMIT();

    for (int it = 0; it < NIT; it++) {
        const int s = it % 3;
        CP_WAIT1();
        __syncthreads();
        if (it + 2 < NIT) { load_stage((it + 2) % 3, it + 2); CP_COMMIT(); }
        GEMM_COMPUTE_STAGE(smp, s);
    }

    float* part = g_part[blockIdx.y];
    const int nbase = n7 * 128;
    #pragma unroll
    for (int mt = 0; mt < 4; mt++) {
        #pragma unroll
        for (int nt = 0; nt < 4; nt++) {
            const int n = nbase + wn * 32 + nt * 8 + 2 * tg;
            #pragma unroll
            for (int half = 0; half < 2; half++) {
                const int m = wm * 64 + mt * 16 + g + half * 8;
                *(float2*)&part[(size_t)m * N_RES + n] =
                    make_float2(acc[mt][nt][half * 2 + 0], acc[mt][nt][half * 2 + 1]);
            }
        }
    }
}

// ===========================================================================
// Per-step reduce + cell update; writes exact state, packed fp16 state, out.
// ===========================================================================
__global__ __launch_bounds__(256) void update_kernel(float* __restrict__ out, int t) {
    const int n = (blockIdx.x * 256 + threadIdx.x) * 4;
    const int b = blockIdx.y;
    const int idx = b * N_RES + n;

    float4 res = *(const float4*)&g_part[0][idx];
    #pragma unroll
    for (int ks = 1; ks < KSPLIT; ks++) {
        float4 p = *(const float4*)&g_part[ks][idx];
        res.x += p.x; res.y += p.y; res.z += p.z; res.w += p.w;
    }

    const float4 prev = *(const float4*)&g_state[idx];
    const size_t mrow = (size_t)t * B_SZ + b;
    const float4 pp = *(const float4*)&g_P[mrow * N_RES + n];
    const float* gr = g_G + mrow * (3 * N_RES);
    const float4 gi = *(const float4*)&gr[n];
    const float4 gf = *(const float4*)&gr[N_RES + n];
    const float4 go = *(const float4*)&gr[2 * N_RES + n];

    float4 s;
    s.x = go.x * (0.9f * gf.x * prev.x + 0.1f * tanhf(gi.x * (pp.x + res.x)));
    s.y = go.y * (0.9f * gf.y * prev.y + 0.1f * tanhf(gi.y * (pp.y + res.y)));
    s.z = go.z * (0.9f * gf.z * prev.z + 0.1f * tanhf(gi.z * (pp.z + res.z)));
    s.w = go.w * (0.9f * gf.w * prev.w + 0.1f * tanhf(gi.w * (pp.w + res.w)));
    if (s.x > 0.5f) s.x -= 0.5f;
    if (s.y > 0.5f) s.y -= 0.5f;
    if (s.z > 0.5f) s.z -= 0.5f;
    if (s.w > 0.5f) s.w -= 0.5f;

    *(float4*)&g_state[idx] = s;
    // fp16 fragment state: (n,n+1) -> one half2, (n+2,n+3) -> next lane (+4 u32)
    const int u0 = fragAH_idx(b, n);
    g_stateP[u0    ] = packh2(s.x, s.y);
    g_stateP[u0 + 4] = packh2(s.z, s.w);
    *(float4*)&out[mrow * MAX_DIM + n] = s;
}

// ---------------- init / padding ------------------------------------------
__global__ __launch_bounds__(256) void init_state_kernel(const float* __restrict__ state0) {
    const int i = blockIdx.x * 256 + threadIdx.x;   // over 128 * 2048 k-pairs
    const int b = i >> 11, n = (i & 2047) * 2;
    const float v0 = state0[(size_t)b * MAX_DIM + n];
    const float v1 = state0[(size_t)b * MAX_DIM + n + 1];
    g_state[b * N_RES + n]     = v0;
    g_state[b * N_RES + n + 1] = v1;
    g_stateP[fragAH_idx(b, n)] = packh2(v0, v1);
}

__global__ __launch_bounds__(256) void pad_out_kernel(float4* __restrict__ out) {
    const int idx = blockIdx.x * 256 + threadIdx.x;
    const int tb = idx >> 7;
    const int c = idx & 127;
    out[(size_t)tb * (MAX_DIM / 4) + (N_RES / 4) + c] = make_float4(0.f, 0.f, 0.f, 0.f);
}

// ===========================================================================
extern "C" void kernel_launch(void* const* d_in, const int* in_sizes, int n_in,
                              void* d_out, int out_size) {
    const float* x      = (const float*)d_in[0];
    const float* state0 = (const float*)d_in[1];
    const float* W_res  = (const float*)d_in[2];
    const float* W_in   = (const float*)d_in[3];
    const float* W_gate = (const float*)d_in[4];
    float* out = (float*)d_out;

    static cudaStream_t s2 = nullptr;
    static cudaEvent_t evFork = nullptr;
    static cudaEvent_t evChunk[N_CHUNKS];
    static bool setup_tried = false;
    static bool overlap_ok = false;
    if (!setup_tried) {
        setup_tried = true;
        cudaFuncSetAttribute(phaseA_frag, cudaFuncAttributeMaxDynamicSharedMemorySize,
                             DSMEM_BYTES);
        cudaFuncSetAttribute(stepB_gemm, cudaFuncAttributeMaxDynamicSharedMemorySize,
                             DSMEM_BYTES);
        cudaStreamCaptureStatus cap = cudaStreamCaptureStatusNone;
        cudaStreamIsCapturing(0, &cap);
        if (cap == cudaStreamCaptureStatusNone) {
            bool ok = (cudaStreamCreateWithFlags(&s2, cudaStreamNonBlocking) == cudaSuccess);
            ok = ok && (cudaEventCreateWithFlags(&evFork, cudaEventDisableTiming) == cudaSuccess);
            for (int c = 0; ok && c < N_CHUNKS; c++)
                ok = (cudaEventCreateWithFlags(&evChunk[c], cudaEventDisableTiming) == cudaSuccess);
            overlap_ok = ok;
        }
    }

    // ---- operand prep on the main stream (R12 topology — clean teardown) ---
    permX_kernel<<<32768, 256>>>(x);
    permWab_kernel<<< 8192, 256>>>(W_in,   N_RES,     0);
    permWab_kernel<<<24576, 256>>>(W_gate, 3 * N_RES, N_RES);
    permWres_kernel<<<32768, 256>>>(W_res);
    init_state_kernel<<<1024, 256>>>(state0);
    pad_out_kernel<<<8192, 256>>>((float4*)out);

    if (overlap_ok) {
        cudaEventRecord(evFork, 0);
        cudaStreamWaitEvent(s2, evFork, 0);
        for (int c = 0; c < N_CHUNKS; c++) {
            phaseA_frag<<<dim3(128, A_CHUNK_TILES), 256, DSMEM_BYTES, s2>>>(c * A_CHUNK_TILES);
            cudaEventRecord(evChunk[c], s2);
        }
        for (int t = 0; t < T_STEPS; t++) {
            stepB_gemm<<<dim3(32, KSPLIT), 256, DSMEM_BYTES>>>();
            if ((t % A_CHUNK_TILES) == 0)
                cudaStreamWaitEvent(0, evChunk[t / A_CHUNK_TILES], 0);
            update_kernel<<<dim3(4, 128), 256>>>(out, t);
        }
    } else {
        for (int c = 0; c < N_CHUNKS; c++)
            phaseA_frag<<<dim3(128, A_CHUNK_TILES), 256, DSMEM_BYTES>>>(c * A_CHUNK_TILES);
        for (int t = 0; t < T_STEPS; t++) {
            stepB_gemm<<<dim3(32, KSPLIT), 256, DSMEM_BYTES>>>();
            update_kernel<<<dim3(4, 128), 256>>>(out, t);
        }
    }
}

// round 16
// speedup vs baseline: 2.6315x; 1.0091x over previous
#include <cuda_runtime.h>
#include <cuda_fp16.h>
#include <cstdint>

#define T_STEPS 128
#define B_SZ    128
#define N_RES   4096
#define IN_DIM  1024
#define MAX_DIM 4608
#define M_A     (T_STEPS * B_SZ)
#define KSPLIT  8                  // phase-B k-splits (32 kblocks of 16k per split)
#define A_CHUNK_TILES 8
#define N_CHUNKS (T_STEPS / A_CHUNK_TILES)   // 16

// 3-stage x 4-kblock pipeline; kblock = 16 k of fp16 = 1024 uint32 per operand
#define KB_PER_STAGE 4
#define STAGE_U32   8192               // 4kb x 1024 A + 4kb x 1024 B (uint32)
#define DSMEM_BYTES (3 * STAGE_U32 * 4)   // 98304

// ---------------- scratch (device globals) ---------------------------------
__device__ uint32_t g_P[(size_t)M_A * N_RES / 2];    // input_part, fp16x2 (134MB)
__device__ float g_G[(size_t)M_A * 3 * N_RES];       // gates, fp32 (precision-critical)
__device__ float g_state[B_SZ * N_RES];              // exact recurrent state
__device__ uint32_t g_stateP[256 * 1024];            // fp16x2 state, fragment-permuted
__device__ uint32_t g_part[KSPLIT][B_SZ * N_RES / 2];// K-split partials, fp16x2 (8MB)

__device__ uint32_t g_xP[(size_t)M_A * IN_DIM / 2];          // x fp16, permuted (A)
__device__ uint32_t g_WabP[(size_t)4 * N_RES * IN_DIM / 2];  // W_in++W_gate fp16 (B)
__device__ uint32_t g_WresP[(size_t)N_RES * N_RES / 2];      // W_res fp16 (B)

// ---------------- helpers ---------------------------------------------------
__device__ __forceinline__ uint32_t packh2(float lo, float hi) {
    __half2 h = __floats2half2_rn(lo, hi);
    return *reinterpret_cast<uint32_t*>(&h);
}
__device__ __forceinline__ float2 unpackh2(uint32_t u) {
    return __half22float2(*reinterpret_cast<__half2*>(&u));
}

__device__ __forceinline__ void mma_f16_16x8x16(float* d, const uint32_t* a,
                                                const uint32_t* b) {
    asm volatile(
        "mma.sync.aligned.m16n8k16.row.col.f32.f16.f16.f32 "
        "{%0,%1,%2,%3}, {%4,%5,%6,%7}, {%8,%9}, {%0,%1,%2,%3};"
        : "+f"(d[0]), "+f"(d[1]), "+f"(d[2]), "+f"(d[3])
        : "r"(a[0]), "r"(a[1]), "r"(a[2]), "r"(a[3]), "r"(b[0]), "r"(b[1]));
}

__device__ __forceinline__ void cp16(void* sm, const void* gm) {
    uint32_t s = (uint32_t)__cvta_generic_to_shared(sm);
    asm volatile("cp.async.cg.shared.global [%0], [%1], 16;" :: "r"(s), "l"(gm));
}
#define CP_COMMIT() asm volatile("cp.async.commit_group;")
#define CP_WAIT1()  asm volatile("cp.async.wait_group 1;")

// uint32 index of the half2 holding (k, k+1) for A-operand element (m, k even).
__device__ __forceinline__ int fragAH_idx(int m, int k) {
    const int kblock = k >> 4, tg = (k >> 1) & 3, khalf = (k >> 3) & 1;
    const int wm = m >> 6, mt = (m >> 4) & 3, rowhalf = (m >> 3) & 1, g = m & 7;
    return kblock * 1024 + wm * 512 + mt * 128 + (g * 4 + tg) * 4 + (rowhalf + 2 * khalf);
}

// ---------------- operand permutation kernels -------------------------------
__global__ __launch_bounds__(256) void permX_kernel(const float* __restrict__ X) {
    const size_t i = (size_t)blockIdx.x * 256 + threadIdx.x;   // m*512 + kpair
    const int m = (int)(i >> 9), k = (int)(i & 511) * 2;
    const float2 v = *(const float2*)&X[(size_t)m * IN_DIM + k];
    const int mtile = m >> 7, mloc = m & 127;
    g_xP[(size_t)mtile * 65536 + fragAH_idx(mloc, k)] = packh2(v.x, v.y);
}

// W[f][k] -> g_WabP (f plays n). layout: [kblock(64)][n7(128)][wn][khalf][lane][nt]
__global__ __launch_bounds__(256) void permWab_kernel(const float* __restrict__ W,
                                                      int nf, int f_off) {
    const size_t i = (size_t)blockIdx.x * 256 + threadIdx.x;   // f*512 + kpair
    if (i >= (size_t)nf * (IN_DIM / 2)) return;
    const int f = (int)(i >> 9), k = (int)(i & 511) * 2;
    const float2 v = *(const float2*)&W[(size_t)f * IN_DIM + k];
    const int fg = f + f_off;
    const int kblock = k >> 4, tg = (k >> 1) & 3, khalf = (k >> 3) & 1;
    const int n7 = fg >> 7, nl = fg & 127;
    const int wn = nl >> 5, nt = (nl >> 3) & 3, g = nl & 7;
    const size_t idx = (size_t)(kblock * 128 + n7) * 1024
                     + wn * 256 + khalf * 128 + (g * 4 + tg) * 4 + nt;
    g_WabP[idx] = packh2(v.x, v.y);
}

// W_res[k][n] -> g_WresP. layout: [kblock(256)][n7(32)][wn][khalf][lane][nt]
__global__ __launch_bounds__(256) void permWres_kernel(const float* __restrict__ W) {
    const size_t i = (size_t)blockIdx.x * 256 + threadIdx.x;   // kpair*4096 + n
    const int k = (int)(i >> 12) * 2, n = (int)(i & 4095);
    const float lo = W[(size_t)k * N_RES + n];
    const float hi = W[(size_t)(k + 1) * N_RES + n];
    const int kblock = k >> 4, tg = (k >> 1) & 3, khalf = (k >> 3) & 1;
    const int n7 = n >> 7, nl = n & 127;
    const int wn = nl >> 5, nt = (nl >> 3) & 3, g = nl & 7;
    const size_t idx = (size_t)(kblock * 32 + n7) * 1024
                     + wn * 256 + khalf * 128 + (g * 4 + tg) * 4 + nt;
    g_WresP[idx] = packh2(lo, hi);
}

// ===========================================================================
// Shared fragment-GEMM mainloop body (fp16; smem already fragment-ordered).
// ===========================================================================
#define GEMM_COMPUTE_STAGE(smp, s)                                             \
    do {                                                                       \
        _Pragma("unroll")                                                      \
        for (int kbl = 0; kbl < KB_PER_STAGE; kbl++) {                         \
            const uint32_t* Ab = (smp) + (s) * STAGE_U32 + kbl * 1024          \
                                 + wm * 512 + lane * 4;                        \
            const uint32_t* Bb = (smp) + (s) * STAGE_U32 + 4096 + kbl * 1024   \
                                 + wn * 256 + lane * 4;                        \
            uint32_t af[4][4];                                                 \
            _Pragma("unroll")                                                  \
            for (int mt = 0; mt < 4; mt++)                                     \
                *(uint4*)af[mt] = *(const uint4*)(Ab + mt * 128);              \
            uint4 b0 = *(const uint4*)(Bb);                                    \
            uint4 b1 = *(const uint4*)(Bb + 128);                              \
            const uint32_t bn0[4] = {b0.x, b0.y, b0.z, b0.w};                  \
            const uint32_t bn1[4] = {b1.x, b1.y, b1.z, b1.w};                  \
            _Pragma("unroll")                                                  \
            for (int mt = 0; mt < 4; mt++)                                     \
                _Pragma("unroll")                                              \
                for (int nt = 0; nt < 4; nt++) {                               \
                    const uint32_t b[2] = {bn0[nt], bn1[nt]};                  \
                    mma_f16_16x8x16(acc[mt][nt], af[mt], b);                   \
                }                                                              \
        }                                                                      \
    } while (0)

// ===========================================================================
// Phase A fragment GEMM: grid (128 n7, A_CHUNK_TILES m-tiles), 256 thr.
// ===========================================================================
__global__ __launch_bounds__(256, 2) void phaseA_frag(int tile0) {
    extern __shared__ uint32_t smp[];
    const int tid  = threadIdx.x;
    const int warp = tid >> 5, lane = tid & 31;
    const int g  = lane >> 2, tg = lane & 3;
    const int wm = warp >> 2, wn = warp & 3;
    const int n7    = blockIdx.x;                       // 0..127
    const int mtile = tile0 + blockIdx.y;
    const uint32_t* Asrc = g_xP + (size_t)mtile * 65536;

    float acc[4][4][4];
    #pragma unroll
    for (int i = 0; i < 4; i++)
        #pragma unroll
        for (int j = 0; j < 4; j++)
            #pragma unroll
            for (int c = 0; c < 4; c++) acc[i][j][c] = 0.f;

    const int NIT = 16;

    auto load_stage = [&](int s, int it) {
        const int kb = it * KB_PER_STAGE;
        #pragma unroll
        for (int r = 0; r < 4; r++) {                   // A
            const int e = tid + r * 256;
            cp16(smp + s * STAGE_U32 + e * 4, Asrc + (size_t)kb * 1024 + e * 4);
        }
        #pragma unroll
        for (int r = 0; r < 4; r++) {                   // B
            const int e = tid + r * 256;
            const int kbl = e >> 8, off = e & 255;
            cp16(smp + s * STAGE_U32 + 4096 + kbl * 1024 + off * 4,
                 g_WabP + ((size_t)(kb + kbl) * 128 + n7) * 1024 + off * 4);
        }
    };

    load_stage(0, 0); CP_COMMIT();
    load_stage(1, 1); CP_COMMIT();

    for (int it = 0; it < NIT; it++) {
        const int s = it % 3;
        CP_WAIT1();
        __syncthreads();
        if (it + 2 < NIT) { load_stage((it + 2) % 3, it + 2); CP_COMMIT(); }
        GEMM_COMPUTE_STAGE(smp, s);
    }

    const bool isP = (n7 < 32);
    #pragma unroll
    for (int mt = 0; mt < 4; mt++) {
        #pragma unroll
        for (int nt = 0; nt < 4; nt++) {
            const int fc = n7 * 128 + wn * 32 + nt * 8 + 2 * tg;
            #pragma unroll
            for (int half = 0; half < 2; half++) {
                const int m = mtile * 128 + wm * 64 + mt * 16 + g + half * 8;
                const float v0 = acc[mt][nt][half * 2 + 0];
                const float v1 = acc[mt][nt][half * 2 + 1];
                if (isP) {
                    g_P[((size_t)m * N_RES + fc) >> 1] = packh2(v0, v1);
                } else {
                    float2 o = make_float2(1.f / (1.f + __expf(-v0)),
                                           1.f / (1.f + __expf(-v1)));
                    *(float2*)&g_G[(size_t)m * (3 * N_RES) + (fc - N_RES)] = o;
                }
            }
        }
    }
}

// ===========================================================================
// Phase B fragment GEMM: grid (32 n7, 8 ksplits), 256 thr, 8 stages of 4 kb.
// Partials stored as fp16x2 (halves update-kernel read traffic).
// ===========================================================================
__global__ __launch_bounds__(256, 2) void stepB_gemm() {
    extern __shared__ uint32_t smp[];
    const int tid  = threadIdx.x;
    const int warp = tid >> 5, lane = tid & 31;
    const int g  = lane >> 2, tg = lane & 3;
    const int wm = warp >> 2, wn = warp & 3;
    const int n7  = blockIdx.x;                         // 0..31
    const int kb0 = blockIdx.y * 32;                    // kblock base (16k each)

    float acc[4][4][4];
    #pragma unroll
    for (int i = 0; i < 4; i++)
        #pragma unroll
        for (int j = 0; j < 4; j++)
            #pragma unroll
            for (int c = 0; c < 4; c++) acc[i][j][c] = 0.f;

    const int NIT = 8;

    auto load_stage = [&](int s, int it) {
        const int kb = kb0 + it * KB_PER_STAGE;
        #pragma unroll
        for (int r = 0; r < 4; r++) {                   // A
            const int e = tid + r * 256;
            cp16(smp + s * STAGE_U32 + e * 4, g_stateP + (size_t)kb * 1024 + e * 4);
        }
        #pragma unroll
        for (int r = 0; r < 4; r++) {                   // B
            const int e = tid + r * 256;
            const int kbl = e >> 8, off = e & 255;
            cp16(smp + s * STAGE_U32 + 4096 + kbl * 1024 + off * 4,
                 g_WresP + ((size_t)(kb + kbl) * 32 + n7) * 1024 + off * 4);
        }
    };

    load_stage(0, 0); CP_COMMIT();
    load_stage(1, 1); CP_COMMIT();

    for (int it = 0; it < NIT; it++) {
        const int s = it % 3;
        CP_WAIT1();
        __syncthreads();
        if (it + 2 < NIT) { load_stage((it + 2) % 3, it + 2); CP_COMMIT(); }
        GEMM_COMPUTE_STAGE(smp, s);
    }

    uint32_t* part = g_part[blockIdx.y];
    const int nbase = n7 * 128;
    #pragma unroll
    for (int mt = 0; mt < 4; mt++) {
        #pragma unroll
        for (int nt = 0; nt < 4; nt++) {
            const int n = nbase + wn * 32 + nt * 8 + 2 * tg;   // even
            #pragma unroll
            for (int half = 0; half < 2; half++) {
                const int m = wm * 64 + mt * 16 + g + half * 8;
                part[((size_t)m * N_RES + n) >> 1] =
                    packh2(acc[mt][nt][half * 2 + 0], acc[mt][nt][half * 2 + 1]);
            }
        }
    }
}

// ===========================================================================
// Per-step reduce + cell update; fp16 partials/P, fp32 gates/state.
// ===========================================================================
__global__ __launch_bounds__(256) void update_kernel(float* __restrict__ out, int t) {
    const int n = (blockIdx.x * 256 + threadIdx.x) * 4;
    const int b = blockIdx.y;
    const int idx = b * N_RES + n;
    const int hidx = idx >> 1;                          // even (n % 4 == 0)

    float4 res = make_float4(0.f, 0.f, 0.f, 0.f);
    #pragma unroll
    for (int ks = 0; ks < KSPLIT; ks++) {
        const uint2 pr = *(const uint2*)&g_part[ks][hidx];
        const float2 fa = unpackh2(pr.x), fb = unpackh2(pr.y);
        res.x += fa.x; res.y += fa.y; res.z += fb.x; res.w += fb.y;
    }

    const float4 prev = *(const float4*)&g_state[idx];
    const size_t mrow = (size_t)t * B_SZ + b;

    const uint2 pu = *(const uint2*)&g_P[(mrow * N_RES + n) >> 1];
    const float2 p01 = unpackh2(pu.x), p23 = unpackh2(pu.y);
    const float4 pp = make_float4(p01.x, p01.y, p23.x, p23.y);

    const float* gr = g_G + mrow * (3 * N_RES);
    const float4 gi = *(const float4*)&gr[n];
    const float4 gf = *(const float4*)&gr[N_RES + n];
    const float4 go = *(const float4*)&gr[2 * N_RES + n];

    float4 s;
    s.x = go.x * (0.9f * gf.x * prev.x + 0.1f * tanhf(gi.x * (pp.x + res.x)));
    s.y = go.y * (0.9f * gf.y * prev.y + 0.1f * tanhf(gi.y * (pp.y + res.y)));
    s.z = go.z * (0.9f * gf.z * prev.z + 0.1f * tanhf(gi.z * (pp.z + res.z)));
    s.w = go.w * (0.9f * gf.w * prev.w + 0.1f * tanhf(gi.w * (pp.w + res.w)));
    if (s.x > 0.5f) s.x -= 0.5f;
    if (s.y > 0.5f) s.y -= 0.5f;
    if (s.z > 0.5f) s.z -= 0.5f;
    if (s.w > 0.5f) s.w -= 0.5f;

    *(float4*)&g_state[idx] = s;
    const int u0 = fragAH_idx(b, n);
    g_stateP[u0    ] = packh2(s.x, s.y);
    g_stateP[u0 + 4] = packh2(s.z, s.w);
    *(float4*)&out[mrow * MAX_DIM + n] = s;
}

// ---------------- init / padding ------------------------------------------
__global__ __launch_bounds__(256) void init_state_kernel(const float* __restrict__ state0) {
    const int i = blockIdx.x * 256 + threadIdx.x;   // over 128 * 2048 k-pairs
    const int b = i >> 11, n = (i & 2047) * 2;
    const float v0 = state0[(size_t)b * MAX_DIM + n];
    const float v1 = state0[(size_t)b * MAX_DIM + n + 1];
    g_state[b * N_RES + n]     = v0;
    g_state[b * N_RES + n + 1] = v1;
    g_stateP[fragAH_idx(b, n)] = packh2(v0, v1);
}

__global__ __launch_bounds__(256) void pad_out_kernel(float4* __restrict__ out) {
    const int idx = blockIdx.x * 256 + threadIdx.x;
    const int tb = idx >> 7;
    const int c = idx & 127;
    out[(size_t)tb * (MAX_DIM / 4) + (N_RES / 4) + c] = make_float4(0.f, 0.f, 0.f, 0.f);
}

// ===========================================================================
extern "C" void kernel_launch(void* const* d_in, const int* in_sizes, int n_in,
                              void* d_out, int out_size) {
    const float* x      = (const float*)d_in[0];
    const float* state0 = (const float*)d_in[1];
    const float* W_res  = (const float*)d_in[2];
    const float* W_in   = (const float*)d_in[3];
    const float* W_gate = (const float*)d_in[4];
    float* out = (float*)d_out;

    static cudaStream_t s2 = nullptr;
    static cudaEvent_t evFork = nullptr;
    static cudaEvent_t evChunk[N_CHUNKS];
    static bool setup_tried = false;
    static bool overlap_ok = false;
    if (!setup_tried) {
        setup_tried = true;
        cudaFuncSetAttribute(phaseA_frag, cudaFuncAttributeMaxDynamicSharedMemorySize,
                             DSMEM_BYTES);
        cudaFuncSetAttribute(stepB_gemm, cudaFuncAttributeMaxDynamicSharedMemorySize,
                             DSMEM_BYTES);
        cudaStreamCaptureStatus cap = cudaStreamCaptureStatusNone;
        cudaStreamIsCapturing(0, &cap);
        if (cap == cudaStreamCaptureStatusNone) {
            bool ok = (cudaStreamCreateWithFlags(&s2, cudaStreamNonBlocking) == cudaSuccess);
            ok = ok && (cudaEventCreateWithFlags(&evFork, cudaEventDisableTiming) == cudaSuccess);
            for (int c = 0; ok && c < N_CHUNKS; c++)
                ok = (cudaEventCreateWithFlags(&evChunk[c], cudaEventDisableTiming) == cudaSuccess);
            overlap_ok = ok;
        }
    }

    // ---- operand prep on the main stream (R14 topology — clean teardown) ---
    permX_kernel<<<32768, 256>>>(x);
    permWab_kernel<<< 8192, 256>>>(W_in,   N_RES,     0);
    permWab_kernel<<<24576, 256>>>(W_gate, 3 * N_RES, N_RES);
    permWres_kernel<<<32768, 256>>>(W_res);
    init_state_kernel<<<1024, 256>>>(state0);
    pad_out_kernel<<<8192, 256>>>((float4*)out);

    if (overlap_ok) {
        cudaEventRecord(evFork, 0);
        cudaStreamWaitEvent(s2, evFork, 0);
        for (int c = 0; c < N_CHUNKS; c++) {
            phaseA_frag<<<dim3(128, A_CHUNK_TILES), 256, DSMEM_BYTES, s2>>>(c * A_CHUNK_TILES);
            cudaEventRecord(evChunk[c], s2);
        }
        for (int t = 0; t < T_STEPS; t++) {
            stepB_gemm<<<dim3(32, KSPLIT), 256, DSMEM_BYTES>>>();
            if ((t % A_CHUNK_TILES) == 0)
                cudaStreamWaitEvent(0, evChunk[t / A_CHUNK_TILES], 0);
            update_kernel<<<dim3(4, 128), 256>>>(out, t);
        }
    } else {
        for (int c = 0; c < N_CHUNKS; c++)
            phaseA_frag<<<dim3(128, A_CHUNK_TILES), 256, DSMEM_BYTES>>>(c * A_CHUNK_TILES);
        for (int t = 0; t < T_STEPS; t++) {
            stepB_gemm<<<dim3(32, KSPLIT), 256, DSMEM_BYTES>>>();
            update_kernel<<<dim3(4, 128), 256>>>(out, t);
        }
    }
}

// round 17
// speedup vs baseline: 2.6506x; 1.0073x over previous
#include <cuda_runtime.h>
#include <cuda_fp16.h>
#include <cstdint>

#define T_STEPS 128
#define B_SZ    128
#define N_RES   4096
#define IN_DIM  1024
#define MAX_DIM 4608
#define M_A     (T_STEPS * B_SZ)
#define KSPLIT  8                  // phase-B k-splits (32 kblocks of 16k per split)
#define N_CHUNKS_A 18              // variable phaseA chunks (head-light)

// 3-stage x 4-kblock pipeline; kblock = 16 k of fp16 = 1024 uint32 per operand
#define KB_PER_STAGE 4
#define STAGE_U32   8192               // 4kb x 1024 A + 4kb x 1024 B (uint32)
#define DSMEM_BYTES (3 * STAGE_U32 * 4)   // 98304

// ---------------- scratch (device globals) ---------------------------------
__device__ uint32_t g_P[(size_t)M_A * N_RES / 2];    // input_part, fp16x2
__device__ float g_G[(size_t)M_A * 3 * N_RES];       // gates, fp32 (precision-critical)
__device__ uint32_t g_stateP[256 * 1024];            // fp16x2 state, fragment-permuted
__device__ uint32_t g_part[KSPLIT][B_SZ * N_RES / 2];// K-split partials, fp16x2

__device__ uint32_t g_xP[(size_t)M_A * IN_DIM / 2];          // x fp16, permuted (A)
__device__ uint32_t g_WabP[(size_t)4 * N_RES * IN_DIM / 2];  // W_in++W_gate fp16 (B)
__device__ uint32_t g_WresP[(size_t)N_RES * N_RES / 2];      // W_res fp16 (B)

// ---------------- helpers ---------------------------------------------------
__device__ __forceinline__ uint32_t packh2(float lo, float hi) {
    __half2 h = __floats2half2_rn(lo, hi);
    return *reinterpret_cast<uint32_t*>(&h);
}
__device__ __forceinline__ float2 unpackh2(uint32_t u) {
    return __half22float2(*reinterpret_cast<__half2*>(&u));
}

__device__ __forceinline__ void mma_f16_16x8x16(float* d, const uint32_t* a,
                                                const uint32_t* b) {
    asm volatile(
        "mma.sync.aligned.m16n8k16.row.col.f32.f16.f16.f32 "
        "{%0,%1,%2,%3}, {%4,%5,%6,%7}, {%8,%9}, {%0,%1,%2,%3};"
        : "+f"(d[0]), "+f"(d[1]), "+f"(d[2]), "+f"(d[3])
        : "r"(a[0]), "r"(a[1]), "r"(a[2]), "r"(a[3]), "r"(b[0]), "r"(b[1]));
}

__device__ __forceinline__ void cp16(void* sm, const void* gm) {
    uint32_t s = (uint32_t)__cvta_generic_to_shared(sm);
    asm volatile("cp.async.cg.shared.global [%0], [%1], 16;" :: "r"(s), "l"(gm));
}
#define CP_COMMIT() asm volatile("cp.async.commit_group;")
#define CP_WAIT1()  asm volatile("cp.async.wait_group 1;")

// uint32 index of the half2 holding (k, k+1) for A-operand element (m, k even).
__device__ __forceinline__ int fragAH_idx(int m, int k) {
    const int kblock = k >> 4, tg = (k >> 1) & 3, khalf = (k >> 3) & 1;
    const int wm = m >> 6, mt = (m >> 4) & 3, rowhalf = (m >> 3) & 1, g = m & 7;
    return kblock * 1024 + wm * 512 + mt * 128 + (g * 4 + tg) * 4 + (rowhalf + 2 * khalf);
}

// ---------------- operand permutation kernels -------------------------------
__global__ __launch_bounds__(256) void permX_kernel(const float* __restrict__ X) {
    const size_t i = (size_t)blockIdx.x * 256 + threadIdx.x;   // m*512 + kpair
    const int m = (int)(i >> 9), k = (int)(i & 511) * 2;
    const float2 v = *(const float2*)&X[(size_t)m * IN_DIM + k];
    const int mtile = m >> 7, mloc = m & 127;
    g_xP[(size_t)mtile * 65536 + fragAH_idx(mloc, k)] = packh2(v.x, v.y);
}

// W[f][k] -> g_WabP (f plays n). layout: [kblock(64)][n7(128)][wn][khalf][lane][nt]
__global__ __launch_bounds__(256) void permWab_kernel(const float* __restrict__ W,
                                                      int nf, int f_off) {
    const size_t i = (size_t)blockIdx.x * 256 + threadIdx.x;   // f*512 + kpair
    if (i >= (size_t)nf * (IN_DIM / 2)) return;
    const int f = (int)(i >> 9), k = (int)(i & 511) * 2;
    const float2 v = *(const float2*)&W[(size_t)f * IN_DIM + k];
    const int fg = f + f_off;
    const int kblock = k >> 4, tg = (k >> 1) & 3, khalf = (k >> 3) & 1;
    const int n7 = fg >> 7, nl = fg & 127;
    const int wn = nl >> 5, nt = (nl >> 3) & 3, g = nl & 7;
    const size_t idx = (size_t)(kblock * 128 + n7) * 1024
                     + wn * 256 + khalf * 128 + (g * 4 + tg) * 4 + nt;
    g_WabP[idx] = packh2(v.x, v.y);
}

// W_res[k][n] -> g_WresP. layout: [kblock(256)][n7(32)][wn][khalf][lane][nt]
__global__ __launch_bounds__(256) void permWres_kernel(const float* __restrict__ W) {
    const size_t i = (size_t)blockIdx.x * 256 + threadIdx.x;   // kpair*4096 + n
    const int k = (int)(i >> 12) * 2, n = (int)(i & 4095);
    const float lo = W[(size_t)k * N_RES + n];
    const float hi = W[(size_t)(k + 1) * N_RES + n];
    const int kblock = k >> 4, tg = (k >> 1) & 3, khalf = (k >> 3) & 1;
    const int n7 = n >> 7, nl = n & 127;
    const int wn = nl >> 5, nt = (nl >> 3) & 3, g = nl & 7;
    const size_t idx = (size_t)(kblock * 32 + n7) * 1024
                     + wn * 256 + khalf * 128 + (g * 4 + tg) * 4 + nt;
    g_WresP[idx] = packh2(lo, hi);
}

// ===========================================================================
// Shared fragment-GEMM mainloop body (fp16; smem already fragment-ordered).
// ===========================================================================
#define GEMM_COMPUTE_STAGE(smp, s)                                             \
    do {                                                                       \
        _Pragma("unroll")                                                      \
        for (int kbl = 0; kbl < KB_PER_STAGE; kbl++) {                         \
            const uint32_t* Ab = (smp) + (s) * STAGE_U32 + kbl * 1024          \
                                 + wm * 512 + lane * 4;                        \
            const uint32_t* Bb = (smp) + (s) * STAGE_U32 + 4096 + kbl * 1024   \
                                 + wn * 256 + lane * 4;                        \
            uint32_t af[4][4];                                                 \
            _Pragma("unroll")                                                  \
            for (int mt = 0; mt < 4; mt++)                                     \
                *(uint4*)af[mt] = *(const uint4*)(Ab + mt * 128);              \
            uint4 b0 = *(const uint4*)(Bb);                                    \
            uint4 b1 = *(const uint4*)(Bb + 128);                              \
            const uint32_t bn0[4] = {b0.x, b0.y, b0.z, b0.w};                  \
            const uint32_t bn1[4] = {b1.x, b1.y, b1.z, b1.w};                  \
            _Pragma("unroll")                                                  \
            for (int mt = 0; mt < 4; mt++)                                     \
                _Pragma("unroll")                                              \
                for (int nt = 0; nt < 4; nt++) {                               \
                    const uint32_t b[2] = {bn0[nt], bn1[nt]};                  \
                    mma_f16_16x8x16(acc[mt][nt], af[mt], b);                   \
                }                                                              \
        }                                                                      \
    } while (0)

// ===========================================================================
// Phase A fragment GEMM: grid (128 n7, chunk m-tiles), 256 thr.
// ===========================================================================
__global__ __launch_bounds__(256, 2) void phaseA_frag(int tile0) {
    extern __shared__ uint32_t smp[];
    const int tid  = threadIdx.x;
    const int warp = tid >> 5, lane = tid & 31;
    const int g  = lane >> 2, tg = lane & 3;
    const int wm = warp >> 2, wn = warp & 3;
    const int n7    = blockIdx.x;                       // 0..127
    const int mtile = tile0 + blockIdx.y;
    const uint32_t* Asrc = g_xP + (size_t)mtile * 65536;

    float acc[4][4][4];
    #pragma unroll
    for (int i = 0; i < 4; i++)
        #pragma unroll
        for (int j = 0; j < 4; j++)
            #pragma unroll
            for (int c = 0; c < 4; c++) acc[i][j][c] = 0.f;

    const int NIT = 16;

    auto load_stage = [&](int s, int it) {
        const int kb = it * KB_PER_STAGE;
        #pragma unroll
        for (int r = 0; r < 4; r++) {                   // A
            const int e = tid + r * 256;
            cp16(smp + s * STAGE_U32 + e * 4, Asrc + (size_t)kb * 1024 + e * 4);
        }
        #pragma unroll
        for (int r = 0; r < 4; r++) {                   // B
            const int e = tid + r * 256;
            const int kbl = e >> 8, off = e & 255;
            cp16(smp + s * STAGE_U32 + 4096 + kbl * 1024 + off * 4,
                 g_WabP + ((size_t)(kb + kbl) * 128 + n7) * 1024 + off * 4);
        }
    };

    load_stage(0, 0); CP_COMMIT();
    load_stage(1, 1); CP_COMMIT();

    for (int it = 0; it < NIT; it++) {
        const int s = it % 3;
        CP_WAIT1();
        __syncthreads();
        if (it + 2 < NIT) { load_stage((it + 2) % 3, it + 2); CP_COMMIT(); }
        GEMM_COMPUTE_STAGE(smp, s);
    }

    const bool isP = (n7 < 32);
    #pragma unroll
    for (int mt = 0; mt < 4; mt++) {
        #pragma unroll
        for (int nt = 0; nt < 4; nt++) {
            const int fc = n7 * 128 + wn * 32 + nt * 8 + 2 * tg;
            #pragma unroll
            for (int half = 0; half < 2; half++) {
                const int m = mtile * 128 + wm * 64 + mt * 16 + g + half * 8;
                const float v0 = acc[mt][nt][half * 2 + 0];
                const float v1 = acc[mt][nt][half * 2 + 1];
                if (isP) {
                    g_P[((size_t)m * N_RES + fc) >> 1] = packh2(v0, v1);
                } else {
                    float2 o = make_float2(1.f / (1.f + __expf(-v0)),
                                           1.f / (1.f + __expf(-v1)));
                    *(float2*)&g_G[(size_t)m * (3 * N_RES) + (fc - N_RES)] = o;
                }
            }
        }
    }
}

// ===========================================================================
// Phase B fragment GEMM: grid (32 n7, 8 ksplits), 256 thr, 8 stages of 4 kb.
// ===========================================================================
__global__ __launch_bounds__(256, 2) void stepB_gemm() {
    extern __shared__ uint32_t smp[];
    const int tid  = threadIdx.x;
    const int warp = tid >> 5, lane = tid & 31;
    const int g  = lane >> 2, tg = lane & 3;
    const int wm = warp >> 2, wn = warp & 3;
    const int n7  = blockIdx.x;                         // 0..31
    const int kb0 = blockIdx.y * 32;                    // kblock base (16k each)

    float acc[4][4][4];
    #pragma unroll
    for (int i = 0; i < 4; i++)
        #pragma unroll
        for (int j = 0; j < 4; j++)
            #pragma unroll
            for (int c = 0; c < 4; c++) acc[i][j][c] = 0.f;

    const int NIT = 8;

    auto load_stage = [&](int s, int it) {
        const int kb = kb0 + it * KB_PER_STAGE;
        #pragma unroll
        for (int r = 0; r < 4; r++) {                   // A
            const int e = tid + r * 256;
            cp16(smp + s * STAGE_U32 + e * 4, g_stateP + (size_t)kb * 1024 + e * 4);
        }
        #pragma unroll
        for (int r = 0; r < 4; r++) {                   // B
            const int e = tid + r * 256;
            const int kbl = e >> 8, off = e & 255;
            cp16(smp + s * STAGE_U32 + 4096 + kbl * 1024 + off * 4,
                 g_WresP + ((size_t)(kb + kbl) * 32 + n7) * 1024 + off * 4);
        }
    };

    load_stage(0, 0); CP_COMMIT();
    load_stage(1, 1); CP_COMMIT();

    for (int it = 0; it < NIT; it++) {
        const int s = it % 3;
        CP_WAIT1();
        __syncthreads();
        if (it + 2 < NIT) { load_stage((it + 2) % 3, it + 2); CP_COMMIT(); }
        GEMM_COMPUTE_STAGE(smp, s);
    }

    uint32_t* part = g_part[blockIdx.y];
    const int nbase = n7 * 128;
    #pragma unroll
    for (int mt = 0; mt < 4; mt++) {
        #pragma unroll
        for (int nt = 0; nt < 4; nt++) {
            const int n = nbase + wn * 32 + nt * 8 + 2 * tg;   // even
            #pragma unroll
            for (int half = 0; half < 2; half++) {
                const int m = wm * 64 + mt * 16 + g + half * 8;
                part[((size_t)m * N_RES + n) >> 1] =
                    packh2(acc[mt][nt][half * 2 + 0], acc[mt][nt][half * 2 + 1]);
            }
        }
    }
}

// ===========================================================================
// Per-step reduce + cell update. prev comes from out row (t-1) (or state0 at
// t=0); out IS the state history, so g_state is gone entirely.
// ===========================================================================
__global__ __launch_bounds__(256) void update_kernel(float* __restrict__ out,
                                                     const float* __restrict__ state0,
                                                     int t) {
    const int n = (blockIdx.x * 256 + threadIdx.x) * 4;
    const int b = blockIdx.y;
    const int idx = b * N_RES + n;
    const int hidx = idx >> 1;                          // even (n % 4 == 0)

    float4 res = make_float4(0.f, 0.f, 0.f, 0.f);
    #pragma unroll
    for (int ks = 0; ks < KSPLIT; ks++) {
        const uint2 pr = *(const uint2*)&g_part[ks][hidx];
        const float2 fa = unpackh2(pr.x), fb = unpackh2(pr.y);
        res.x += fa.x; res.y += fa.y; res.z += fb.x; res.w += fb.y;
    }

    const float* prev_src = (t == 0)
        ? (state0 + (size_t)b * MAX_DIM + n)
        : (out + ((size_t)(t - 1) * B_SZ + b) * MAX_DIM + n);
    const float4 prev = *(const float4*)prev_src;

    const size_t mrow = (size_t)t * B_SZ + b;
    const uint2 pu = *(const uint2*)&g_P[(mrow * N_RES + n) >> 1];
    const float2 p01 = unpackh2(pu.x), p23 = unpackh2(pu.y);
    const float4 pp = make_float4(p01.x, p01.y, p23.x, p23.y);

    const float* gr = g_G + mrow * (3 * N_RES);
    const float4 gi = *(const float4*)&gr[n];
    const float4 gf = *(const float4*)&gr[N_RES + n];
    const float4 go = *(const float4*)&gr[2 * N_RES + n];

    float4 s;
    s.x = go.x * (0.9f * gf.x * prev.x + 0.1f * tanhf(gi.x * (pp.x + res.x)));
    s.y = go.y * (0.9f * gf.y * prev.y + 0.1f * tanhf(gi.y * (pp.y + res.y)));
    s.z = go.z * (0.9f * gf.z * prev.z + 0.1f * tanhf(gi.z * (pp.z + res.z)));
    s.w = go.w * (0.9f * gf.w * prev.w + 0.1f * tanhf(gi.w * (pp.w + res.w)));
    if (s.x > 0.5f) s.x -= 0.5f;
    if (s.y > 0.5f) s.y -= 0.5f;
    if (s.z > 0.5f) s.z -= 0.5f;
    if (s.w > 0.5f) s.w -= 0.5f;

    const int u0 = fragAH_idx(b, n);
    g_stateP[u0    ] = packh2(s.x, s.y);
    g_stateP[u0 + 4] = packh2(s.z, s.w);
    *(float4*)&out[mrow * MAX_DIM + n] = s;
}

// ---------------- init / padding ------------------------------------------
__global__ __launch_bounds__(256) void init_state_kernel(const float* __restrict__ state0) {
    const int i = blockIdx.x * 256 + threadIdx.x;   // over 128 * 2048 k-pairs
    const int b = i >> 11, n = (i & 2047) * 2;
    const float v0 = state0[(size_t)b * MAX_DIM + n];
    const float v1 = state0[(size_t)b * MAX_DIM + n + 1];
    g_stateP[fragAH_idx(b, n)] = packh2(v0, v1);
}

__global__ __launch_bounds__(256) void pad_out_kernel(float4* __restrict__ out) {
    const int idx = blockIdx.x * 256 + threadIdx.x;
    const int tb = idx >> 7;
    const int c = idx & 127;
    out[(size_t)tb * (MAX_DIM / 4) + (N_RES / 4) + c] = make_float4(0.f, 0.f, 0.f, 0.f);
}

// ===========================================================================
extern "C" void kernel_launch(void* const* d_in, const int* in_sizes, int n_in,
                              void* d_out, int out_size) {
    const float* x      = (const float*)d_in[0];
    const float* state0 = (const float*)d_in[1];
    const float* W_res  = (const float*)d_in[2];
    const float* W_in   = (const float*)d_in[3];
    const float* W_gate = (const float*)d_in[4];
    float* out = (float*)d_out;

    // head-light phaseA chunk sizes (in 128-row m-tiles); sum = 128
    static const int chunk_sz[N_CHUNKS_A] =
        {2, 2, 4, 8, 8, 8, 8, 8, 8, 8, 8, 8, 8, 8, 8, 8, 8, 8};

    static cudaStream_t s2 = nullptr;
    static cudaEvent_t evFork = nullptr;
    static cudaEvent_t evChunk[N_CHUNKS_A];
    static bool setup_tried = false;
    static bool overlap_ok = false;
    if (!setup_tried) {
        setup_tried = true;
        cudaFuncSetAttribute(phaseA_frag, cudaFuncAttributeMaxDynamicSharedMemorySize,
                             DSMEM_BYTES);
        cudaFuncSetAttribute(stepB_gemm, cudaFuncAttributeMaxDynamicSharedMemorySize,
                             DSMEM_BYTES);
        cudaStreamCaptureStatus cap = cudaStreamCaptureStatusNone;
        cudaStreamIsCapturing(0, &cap);
        if (cap == cudaStreamCaptureStatusNone) {
            bool ok = (cudaStreamCreateWithFlags(&s2, cudaStreamNonBlocking) == cudaSuccess);
            ok = ok && (cudaEventCreateWithFlags(&evFork, cudaEventDisableTiming) == cudaSuccess);
            for (int c = 0; ok && c < N_CHUNKS_A; c++)
                ok = (cudaEventCreateWithFlags(&evChunk[c], cudaEventDisableTiming) == cudaSuccess);
            overlap_ok = ok;
        }
    }

    // ---- operand prep on the main stream ------------------------------------
    permX_kernel<<<32768, 256>>>(x);
    permWab_kernel<<< 8192, 256>>>(W_in,   N_RES,     0);
    permWab_kernel<<<24576, 256>>>(W_gate, 3 * N_RES, N_RES);
    permWres_kernel<<<32768, 256>>>(W_res);
    init_state_kernel<<<1024, 256>>>(state0);

    if (overlap_ok) {
        cudaEventRecord(evFork, 0);
        cudaStreamWaitEvent(s2, evFork, 0);
        pad_out_kernel<<<8192, 256, 0, s2>>>((float4*)out);
        int tile0 = 0;
        for (int c = 0; c < N_CHUNKS_A; c++) {
            phaseA_frag<<<dim3(128, chunk_sz[c]), 256, DSMEM_BYTES, s2>>>(tile0);
            tile0 += chunk_sz[c];
            cudaEventRecord(evChunk[c], s2);
        }

        int next_chunk = 0, next_boundary = 0;
        for (int t = 0; t < T_STEPS; t++) {
            stepB_gemm<<<dim3(32, KSPLIT), 256, DSMEM_BYTES>>>();
            if (t == next_boundary) {
                cudaStreamWaitEvent(0, evChunk[next_chunk], 0);
                next_boundary += chunk_sz[next_chunk];
                next_chunk++;
            }
            update_kernel<<<dim3(4, 128), 256>>>(out, state0, t);
        }
    } else {
        pad_out_kernel<<<8192, 256>>>((float4*)out);
        int tile0 = 0;
        for (int c = 0; c < N_CHUNKS_A; c++) {
            phaseA_frag<<<dim3(128, chunk_sz[c]), 256, DSMEM_BYTES>>>(tile0);
            tile0 += chunk_sz[c];
        }
        for (int t = 0; t < T_STEPS; t++) {
            stepB_gemm<<<dim3(32, KSPLIT), 256, DSMEM_BYTES>>>();
            update_kernel<<<dim3(4, 128), 256>>>(out, state0, t);
        }
    }
}